// round 12
// baseline (speedup 1.0000x reference)
#include <cuda_runtime.h>
#include <cuda_bf16.h>
#include <cstdint>

#define B_  8
#define S_  1024
#define H_  1024
#define NH_ 16
#define HD_ 64
#define MROWS (B_ * S_)
#define NBIG (MROWS * H_)

// Pre-converted input activations (hi/lo bf16)
__device__ __nv_bfloat16 g_xqh[NBIG], g_xql[NBIG];
__device__ __nv_bfloat16 g_xkh[NBIG], g_xkl[NBIG];
__device__ __nv_bfloat16 g_xvh[NBIG], g_xvl[NBIG];
// Projections (written split by qkv GEMM, consumed by attention)
__device__ __nv_bfloat16 g_qh[NBIG], g_ql[NBIG];
__device__ __nv_bfloat16 g_kh[NBIG], g_kl[NBIG];
__device__ __nv_bfloat16 g_vh[NBIG], g_vl[NBIG];
// Attention output (written split by attention, consumed by O GEMM)
__device__ __nv_bfloat16 g_ah[NBIG], g_al[NBIG];
// Weights (hi/lo)
__device__ __nv_bfloat16 g_wqh[H_ * H_], g_wql[H_ * H_];
__device__ __nv_bfloat16 g_wkh[H_ * H_], g_wkl[H_ * H_];
__device__ __nv_bfloat16 g_wvh[H_ * H_], g_wvl[H_ * H_];
__device__ __nv_bfloat16 g_woh[H_ * H_], g_wol[H_ * H_];

__device__ __forceinline__ uint32_t smem_u32(const void* p) {
    uint32_t a;
    asm("{ .reg .u64 t; cvta.to.shared.u64 t, %1; cvt.u32.u64 %0, t; }"
        : "=r"(a) : "l"(p));
    return a;
}

#define LDMX4(r0, r1, r2, r3, addr) \
    asm volatile("ldmatrix.sync.aligned.m8n8.x4.shared.b16 {%0,%1,%2,%3}, [%4];" \
                 : "=r"(r0), "=r"(r1), "=r"(r2), "=r"(r3) : "r"(addr))

#define LDMX4T(r0, r1, r2, r3, addr) \
    asm volatile("ldmatrix.sync.aligned.m8n8.x4.trans.shared.b16 {%0,%1,%2,%3}, [%4];" \
                 : "=r"(r0), "=r"(r1), "=r"(r2), "=r"(r3) : "r"(addr))

#define MMA16816(d, a, b) \
    asm volatile("mma.sync.aligned.m16n8k16.row.col.f32.bf16.bf16.f32 " \
                 "{%0,%1,%2,%3}, {%4,%5,%6,%7}, {%8,%9}, {%0,%1,%2,%3};" \
                 : "+f"((d)[0]), "+f"((d)[1]), "+f"((d)[2]), "+f"((d)[3]) \
                 : "r"((a)[0]), "r"((a)[1]), "r"((a)[2]), "r"((a)[3]), \
                   "r"((b)[0]), "r"((b)[1]))

#define CPA16(dst, src) \
    asm volatile("cp.async.cg.shared.global [%0], [%1], 16;" :: "r"(dst), "l"(src))
#define CP_COMMIT() asm volatile("cp.async.commit_group;")
#define CP_WAIT(n)  asm volatile("cp.async.wait_group %0;" :: "n"(n))

__device__ __forceinline__ uint32_t pack_hi(float x, float y) {
    __nv_bfloat162 h = __float22bfloat162_rn(make_float2(x, y));
    return *(uint32_t*)&h;
}
__device__ __forceinline__ uint32_t pack_lo(float x, float y, uint32_t hi) {
    __nv_bfloat162 h = *(__nv_bfloat162*)&hi;
    __nv_bfloat162 l = __float22bfloat162_rn(make_float2(
        x - __bfloat162float(h.x), y - __bfloat162float(h.y)));
    return *(uint32_t*)&l;
}

// ===========================================================================
// fp32 -> bf16 hi/lo split converts. 4 independent float4 loads per iter
// (MLP=4), uint4 stores.
// ===========================================================================
__device__ __forceinline__ void conv_chunk(
    const float* __restrict__ src, __nv_bfloat16* __restrict__ hi,
    __nv_bfloat16* __restrict__ lo, int i)
{
    float4 a = ((const float4*)src)[4 * i];
    float4 b = ((const float4*)src)[4 * i + 1];
    float4 c = ((const float4*)src)[4 * i + 2];
    float4 d = ((const float4*)src)[4 * i + 3];
    uint32_t h0 = pack_hi(a.x, a.y), h1 = pack_hi(a.z, a.w);
    uint32_t h2 = pack_hi(b.x, b.y), h3 = pack_hi(b.z, b.w);
    uint32_t h4 = pack_hi(c.x, c.y), h5 = pack_hi(c.z, c.w);
    uint32_t h6 = pack_hi(d.x, d.y), h7 = pack_hi(d.z, d.w);
    ((uint4*)hi)[2 * i]     = make_uint4(h0, h1, h2, h3);
    ((uint4*)hi)[2 * i + 1] = make_uint4(h4, h5, h6, h7);
    uint4 lo0 = make_uint4(pack_lo(a.x, a.y, h0), pack_lo(a.z, a.w, h1),
                           pack_lo(b.x, b.y, h2), pack_lo(b.z, b.w, h3));
    uint4 lo1 = make_uint4(pack_lo(c.x, c.y, h4), pack_lo(c.z, c.w, h5),
                           pack_lo(d.x, d.y, h6), pack_lo(d.z, d.w, h7));
    ((uint4*)lo)[2 * i]     = lo0;
    ((uint4*)lo)[2 * i + 1] = lo1;
}

__global__ __launch_bounds__(256)
void conv_hl(const float* __restrict__ src, __nv_bfloat16* __restrict__ hi,
             __nv_bfloat16* __restrict__ lo, int n16)
{
    for (int i = blockIdx.x * blockDim.x + threadIdx.x; i < n16;
         i += gridDim.x * blockDim.x)
        conv_chunk(src, hi, lo, i);
}

// Dual-array convert (two weight matrices per launch; blockIdx.y selects).
__global__ __launch_bounds__(256)
void conv_hl2(const float* __restrict__ s0, __nv_bfloat16* __restrict__ h0,
              __nv_bfloat16* __restrict__ l0,
              const float* __restrict__ s1, __nv_bfloat16* __restrict__ h1,
              __nv_bfloat16* __restrict__ l1, int n16)
{
    const float* src = blockIdx.y ? s1 : s0;
    __nv_bfloat16* hi = blockIdx.y ? h1 : h0;
    __nv_bfloat16* lo = blockIdx.y ? l1 : l0;
    for (int i = blockIdx.x * blockDim.x + threadIdx.x; i < n16;
         i += gridDim.x * blockDim.x)
        conv_chunk(src, hi, lo, i);
}

// ===========================================================================
// Pre-converted bf16 hi/lo GEMM (R11-exact). 128x128 tile, BK=64,
// 2-stage cp.async pipeline. Epilogue fp32 or split bf16.
// ===========================================================================
#define HLTILE_B  (128 * 72 * 2)
#define HLSTAGE_B (4 * HLTILE_B)
#define GEMM_SMEM (2 * HLSTAGE_B)       // 147456 B

__device__ __forceinline__ void hl_issue(
    uint32_t stage, const __nv_bfloat16* Ah, const __nv_bfloat16* Al,
    const __nv_bfloat16* Wh, const __nv_bfloat16* Wl, int k0, int tid)
{
    const __nv_bfloat16* srcs[4] = { Ah, Al, Wh, Wl };
#pragma unroll
    for (int t = 0; t < 4; t++) {
        const uint32_t db = stage + t * HLTILE_B;
        const __nv_bfloat16* sb = srcs[t] + k0;
#pragma unroll
        for (int j = 0; j < 4; j++) {
            const int idx = tid + j * 256;
            const int row = idx >> 3;
            const int c   = idx & 7;
            CPA16(db + row * 144 + c * 16, sb + (size_t)row * H_ + c * 8);
        }
    }
}

template<int SPLIT>
__device__ __forceinline__ void gemm_hl_body(
    const __nv_bfloat16* __restrict__ Ah, const __nv_bfloat16* __restrict__ Al,
    const __nv_bfloat16* __restrict__ Wh, const __nv_bfloat16* __restrict__ Wl,
    const float* __restrict__ bias, float* __restrict__ C,
    __nv_bfloat16* __restrict__ Ch, __nv_bfloat16* __restrict__ Cl,
    char* gsm, int bm0, int bn0)
{
    const int tid  = threadIdx.x;
    const int wid  = tid >> 5;
    const int lane = tid & 31;
    const int wm   = wid & 1;
    const int wn   = wid >> 1;

    const uint32_t ubase = smem_u32(gsm);
    const uint32_t aLOff = (uint32_t)((wm * 64 + (lane & 15)) * 144 + (lane >> 4) * 16);
    const uint32_t bLOff = (uint32_t)((wn * 32 + ((lane >> 4) & 1) * 8 + (lane & 7)) * 144
                                      + ((lane >> 3) & 1) * 16);

    const __nv_bfloat16* At_h = Ah + (size_t)bm0 * H_;
    const __nv_bfloat16* At_l = Al + (size_t)bm0 * H_;
    const __nv_bfloat16* Wt_h = Wh + (size_t)bn0 * H_;
    const __nv_bfloat16* Wt_l = Wl + (size_t)bn0 * H_;

    float acc[4][4][4];
#pragma unroll
    for (int mi = 0; mi < 4; mi++)
#pragma unroll
        for (int nj = 0; nj < 4; nj++)
#pragma unroll
            for (int e = 0; e < 4; e++) acc[mi][nj][e] = 0.f;

    hl_issue(ubase, At_h, At_l, Wt_h, Wt_l, 0, tid);
    CP_COMMIT();

    for (int c = 0; c < 16; c++) {
        if (c < 15) {
            hl_issue(ubase + (uint32_t)((c + 1) & 1) * HLSTAGE_B,
                     At_h, At_l, Wt_h, Wt_l, (c + 1) * 64, tid);
            CP_COMMIT();
            CP_WAIT(1);
        } else {
            CP_WAIT(0);
        }
        __syncthreads();

        const uint32_t ub  = ubase + (uint32_t)(c & 1) * HLSTAGE_B;
        const uint32_t bAh = ub;
        const uint32_t bAl = ub + HLTILE_B;
        const uint32_t bWh = ub + 2 * HLTILE_B;
        const uint32_t bWl = ub + 3 * HLTILE_B;

#pragma unroll
        for (int ks = 0; ks < 4; ks++) {
            const uint32_t kb = (uint32_t)(ks * 32);
            uint32_t ah[4][4], al[4][4];
#pragma unroll
            for (int mi = 0; mi < 4; mi++) {
                const uint32_t rowb = (uint32_t)(mi * 16 * 144) + aLOff + kb;
                LDMX4(ah[mi][0], ah[mi][1], ah[mi][2], ah[mi][3], bAh + rowb);
                LDMX4(al[mi][0], al[mi][1], al[mi][2], al[mi][3], bAl + rowb);
            }
            uint32_t bh[4][2], bl[4][2];
#pragma unroll
            for (int pr = 0; pr < 2; pr++) {
                const uint32_t rowb = (uint32_t)(pr * 16 * 144) + bLOff + kb;
                LDMX4(bh[pr * 2][0], bh[pr * 2][1], bh[pr * 2 + 1][0], bh[pr * 2 + 1][1], bWh + rowb);
                LDMX4(bl[pr * 2][0], bl[pr * 2][1], bl[pr * 2 + 1][0], bl[pr * 2 + 1][1], bWl + rowb);
            }
#pragma unroll
            for (int mi = 0; mi < 4; mi++)
#pragma unroll
                for (int nj = 0; nj < 4; nj++) {
                    MMA16816(acc[mi][nj], ah[mi], bh[nj]);
                    MMA16816(acc[mi][nj], al[mi], bh[nj]);
                    MMA16816(acc[mi][nj], ah[mi], bl[nj]);
                }
        }
        __syncthreads();
    }

#pragma unroll
    for (int mi = 0; mi < 4; mi++) {
        const int r0 = bm0 + wm * 64 + mi * 16 + (lane >> 2);
#pragma unroll
        for (int nj = 0; nj < 4; nj++) {
            const int col = bn0 + wn * 32 + nj * 8 + (lane & 3) * 2;
            const float b0 = bias[col], b1 = bias[col + 1];
            float o0x = acc[mi][nj][0] + b0, o0y = acc[mi][nj][1] + b1;
            float o1x = acc[mi][nj][2] + b0, o1y = acc[mi][nj][3] + b1;
            if (SPLIT) {
                uint32_t h0 = pack_hi(o0x, o0y);
                uint32_t h1 = pack_hi(o1x, o1y);
                *(uint32_t*)(Ch + (size_t)r0 * H_ + col)       = h0;
                *(uint32_t*)(Ch + (size_t)(r0 + 8) * H_ + col) = h1;
                *(uint32_t*)(Cl + (size_t)r0 * H_ + col)       = pack_lo(o0x, o0y, h0);
                *(uint32_t*)(Cl + (size_t)(r0 + 8) * H_ + col) = pack_lo(o1x, o1y, h1);
            } else {
                *(float2*)(C + (size_t)r0 * H_ + col)       = make_float2(o0x, o0y);
                *(float2*)(C + (size_t)(r0 + 8) * H_ + col) = make_float2(o1x, o1y);
            }
        }
    }
}

// Fused Q/K/V projections: split bf16 outputs.
__global__ __launch_bounds__(256, 1)
void qkv_hl(const float* __restrict__ bq, const float* __restrict__ bk,
            const float* __restrict__ bv)
{
    extern __shared__ char gsm[];
    const __nv_bfloat16 *Ah, *Al, *Wh, *Wl;
    const float* bias;
    __nv_bfloat16 *Ch, *Cl;
    if (blockIdx.z == 0)      { Ah = g_xqh; Al = g_xql; Wh = g_wqh; Wl = g_wql; bias = bq; Ch = g_qh; Cl = g_ql; }
    else if (blockIdx.z == 1) { Ah = g_xkh; Al = g_xkl; Wh = g_wkh; Wl = g_wkl; bias = bk; Ch = g_kh; Cl = g_kl; }
    else                      { Ah = g_xvh; Al = g_xvl; Wh = g_wvh; Wl = g_wvl; bias = bv; Ch = g_vh; Cl = g_vl; }
    gemm_hl_body<1>(Ah, Al, Wh, Wl, bias, nullptr, Ch, Cl, gsm,
                    blockIdx.y * 128, blockIdx.x * 128);
}

__global__ __launch_bounds__(256, 1)
void gemm_o_hl(const float* __restrict__ bias, float* __restrict__ C)
{
    extern __shared__ char gsm[];
    gemm_hl_body<0>(g_ah, g_al, g_woh, g_wol, bias, C, nullptr, nullptr, gsm,
                    blockIdx.y * 128, blockIdx.x * 128);
}

// ===========================================================================
// Tensor-core flash attention on pre-split K/V (R11-exact).
// ===========================================================================
#define AT_TILE_B  (64 * 144)
#define AT_STAGE_B (4 * AT_TILE_B)
#define ATTN_SMEM  (2 * AT_STAGE_B)

__device__ __forceinline__ void attn_issue(
    uint32_t stage, const __nv_bfloat16* Kh, const __nv_bfloat16* Kl,
    const __nv_bfloat16* Vh, const __nv_bfloat16* Vl, int tid)
{
    const __nv_bfloat16* srcs[4] = { Kh, Kl, Vh, Vl };
#pragma unroll
    for (int t = 0; t < 4; t++) {
        const uint32_t db = stage + t * AT_TILE_B;
        const __nv_bfloat16* sb = srcs[t];
#pragma unroll
        for (int j = 0; j < 2; j++) {
            const int idx = tid + j * 256;
            const int row = idx >> 3;
            const int c   = idx & 7;
            CPA16(db + row * 144 + c * 16, sb + (size_t)row * H_ + c * 8);
        }
    }
}

__global__ __launch_bounds__(256, 1)
void attn_tc(const int* __restrict__ mask)
{
    extern __shared__ char asmem[];
    __shared__ uint32_t s_mb[32];

    const int tid  = threadIdx.x;
    const int wid  = tid >> 5;
    const int lane = tid & 31;
    const int qt = blockIdx.x;
    const int h  = blockIdx.y;
    const int b  = blockIdx.z;

    const uint32_t ubase = smem_u32(asmem);

    const int r0 = wid * 16 + (lane >> 2);
    const size_t qoff = ((size_t)(b * S_ + qt * 128)) * H_ + h * HD_;
    const __nv_bfloat16* Qhb = g_qh + qoff;
    const __nv_bfloat16* Qlb = g_ql + qoff;
    uint32_t qh[4][4], ql[4][4];
#pragma unroll
    for (int ks = 0; ks < 4; ks++) {
        const int kb = ks * 16 + (lane & 3) * 2;
        qh[ks][0] = *(const uint32_t*)(Qhb + (size_t)r0 * H_ + kb);
        qh[ks][1] = *(const uint32_t*)(Qhb + (size_t)(r0 + 8) * H_ + kb);
        qh[ks][2] = *(const uint32_t*)(Qhb + (size_t)r0 * H_ + kb + 8);
        qh[ks][3] = *(const uint32_t*)(Qhb + (size_t)(r0 + 8) * H_ + kb + 8);
        ql[ks][0] = *(const uint32_t*)(Qlb + (size_t)r0 * H_ + kb);
        ql[ks][1] = *(const uint32_t*)(Qlb + (size_t)(r0 + 8) * H_ + kb);
        ql[ks][2] = *(const uint32_t*)(Qlb + (size_t)r0 * H_ + kb + 8);
        ql[ks][3] = *(const uint32_t*)(Qlb + (size_t)(r0 + 8) * H_ + kb + 8);
    }

    {
        int mv[4];
#pragma unroll
        for (int j = 0; j < 4; j++)
            mv[j] = mask[(size_t)b * S_ + (wid * 4 + j) * 32 + lane];
#pragma unroll
        for (int j = 0; j < 4; j++) {
            unsigned bv = __ballot_sync(0xffffffffu, mv[j] != 0);
            if (lane == 0) s_mb[wid * 4 + j] = bv;
        }
    }

    float oacc[8][4];
#pragma unroll
    for (int nj = 0; nj < 8; nj++)
#pragma unroll
        for (int e = 0; e < 4; e++) oacc[nj][e] = 0.f;
    float m0 = -1e30f, m1 = -1e30f, l0 = 0.f, l1 = 0.f;

    const size_t koff = (size_t)b * S_ * H_ + h * HD_;
    const __nv_bfloat16* Khb = g_kh + koff;
    const __nv_bfloat16* Klb = g_kl + koff;
    const __nv_bfloat16* Vhb = g_vh + koff;
    const __nv_bfloat16* Vlb = g_vl + koff;

    attn_issue(ubase, Khb, Klb, Vhb, Vlb, tid);
    CP_COMMIT();

    for (int kt = 0; kt < 16; kt++) {
        const int sel = kt & 1;
        CP_WAIT(0);
        __syncthreads();
        if (kt < 15) {
            const size_t toff = (size_t)(kt + 1) * 64 * H_;
            attn_issue(ubase + (uint32_t)(sel ^ 1) * AT_STAGE_B,
                       Khb + toff, Klb + toff, Vhb + toff, Vlb + toff, tid);
            CP_COMMIT();
        }
        const uint32_t mw0 = s_mb[2 * kt];
        const uint32_t mw1 = s_mb[2 * kt + 1];
        const uint32_t ub  = ubase + (uint32_t)sel * AT_STAGE_B;
        const uint32_t bKh = ub;
        const uint32_t bKl = ub + AT_TILE_B;
        const uint32_t bVh = ub + 2 * AT_TILE_B;
        const uint32_t bVl = ub + 3 * AT_TILE_B;

        float sacc[8][4];
#pragma unroll
        for (int nj = 0; nj < 8; nj++)
#pragma unroll
            for (int e = 0; e < 4; e++) sacc[nj][e] = 0.f;

#pragma unroll
        for (int ks = 0; ks < 4; ks++) {
            uint32_t bh[8][2], bl[8][2];
#pragma unroll
            for (int g = 0; g < 4; g++) {
                const uint32_t rowb =
                    (uint32_t)((g * 16 + ((lane >> 4) & 1) * 8 + (lane & 7)) * 144
                               + ks * 32 + ((lane >> 3) & 1) * 16);
                LDMX4(bh[2 * g][0], bh[2 * g][1], bh[2 * g + 1][0], bh[2 * g + 1][1], bKh + rowb);
                LDMX4(bl[2 * g][0], bl[2 * g][1], bl[2 * g + 1][0], bl[2 * g + 1][1], bKl + rowb);
            }
#pragma unroll
            for (int nj = 0; nj < 8; nj++) {
                MMA16816(sacc[nj], qh[ks], bh[nj]);
                MMA16816(sacc[nj], ql[ks], bh[nj]);
                MMA16816(sacc[nj], qh[ks], bl[nj]);
            }
        }

        const int shb = (lane & 3) * 2;
        float mx0 = -1e30f, mx1 = -1e30f;
#pragma unroll
        for (int nj = 0; nj < 8; nj++) {
            const uint32_t w = (nj < 4) ? mw0 : mw1;
            const int sh = (nj & 3) * 8 + shb;
            const bool k0 = (w >> sh) & 1;
            const bool k1 = (w >> (sh + 1)) & 1;
            float s0 = k0 ? -1e30f : sacc[nj][0] * 0.03125f;
            float s1 = k1 ? -1e30f : sacc[nj][1] * 0.03125f;
            float s2 = k0 ? -1e30f : sacc[nj][2] * 0.03125f;
            float s3 = k1 ? -1e30f : sacc[nj][3] * 0.03125f;
            sacc[nj][0] = s0; sacc[nj][1] = s1; sacc[nj][2] = s2; sacc[nj][3] = s3;
            mx0 = fmaxf(mx0, fmaxf(s0, s1));
            mx1 = fmaxf(mx1, fmaxf(s2, s3));
        }
        mx0 = fmaxf(mx0, __shfl_xor_sync(0xffffffffu, mx0, 1));
        mx0 = fmaxf(mx0, __shfl_xor_sync(0xffffffffu, mx0, 2));
        mx1 = fmaxf(mx1, __shfl_xor_sync(0xffffffffu, mx1, 1));
        mx1 = fmaxf(mx1, __shfl_xor_sync(0xffffffffu, mx1, 2));

        const float nm0 = fmaxf(m0, mx0);
        const float nm1 = fmaxf(m1, mx1);
        const float f0 = __expf(m0 - nm0);
        const float f1 = __expf(m1 - nm1);
        m0 = nm0; m1 = nm1;
        l0 *= f0;  l1 *= f1;
#pragma unroll
        for (int nj = 0; nj < 8; nj++) {
            oacc[nj][0] *= f0; oacc[nj][1] *= f0;
            oacc[nj][2] *= f1; oacc[nj][3] *= f1;
        }

        uint32_t pHa[8], pHb[8], pLa[8], pLb[8];
        float ps0 = 0.f, ps1 = 0.f;
#pragma unroll
        for (int nj = 0; nj < 8; nj++) {
            float p0 = __expf(sacc[nj][0] - nm0);
            float p1 = __expf(sacc[nj][1] - nm0);
            float p2 = __expf(sacc[nj][2] - nm1);
            float p3 = __expf(sacc[nj][3] - nm1);
            ps0 += p0 + p1;
            ps1 += p2 + p3;
            pHa[nj] = pack_hi(p0, p1);  pLa[nj] = pack_lo(p0, p1, pHa[nj]);
            pHb[nj] = pack_hi(p2, p3);  pLb[nj] = pack_lo(p2, p3, pHb[nj]);
        }
        l0 += ps0;
        l1 += ps1;

#pragma unroll
        for (int kk = 0; kk < 4; kk++) {
            uint32_t aH[4] = { pHa[2 * kk], pHb[2 * kk], pHa[2 * kk + 1], pHb[2 * kk + 1] };
            uint32_t aL[4] = { pLa[2 * kk], pLb[2 * kk], pLa[2 * kk + 1], pLb[2 * kk + 1] };
#pragma unroll
            for (int njp = 0; njp < 8; njp += 2) {
                const uint32_t rowb =
                    (uint32_t)((kk * 16 + (lane & 15)) * 144
                               + (njp + ((lane >> 4) & 1)) * 16);
                uint32_t vh[2][2], vl[2][2];
                LDMX4T(vh[0][0], vh[0][1], vh[1][0], vh[1][1], bVh + rowb);
                LDMX4T(vl[0][0], vl[0][1], vl[1][0], vl[1][1], bVl + rowb);
                MMA16816(oacc[njp],     aH, vh[0]);
                MMA16816(oacc[njp],     aL, vh[0]);
                MMA16816(oacc[njp],     aH, vl[0]);
                MMA16816(oacc[njp + 1], aH, vh[1]);
                MMA16816(oacc[njp + 1], aL, vh[1]);
                MMA16816(oacc[njp + 1], aH, vl[1]);
            }
        }
    }

    l0 += __shfl_xor_sync(0xffffffffu, l0, 1);
    l0 += __shfl_xor_sync(0xffffffffu, l0, 2);
    l1 += __shfl_xor_sync(0xffffffffu, l1, 1);
    l1 += __shfl_xor_sync(0xffffffffu, l1, 2);
    const float rl0 = 1.f / l0;
    const float rl1 = 1.f / l1;

    __nv_bfloat16* Ahb = g_ah + qoff;
    __nv_bfloat16* Alb = g_al + qoff;
#pragma unroll
    for (int nj = 0; nj < 8; nj++) {
        const int colb = nj * 8 + (lane & 3) * 2;
        float x0 = oacc[nj][0] * rl0, y0 = oacc[nj][1] * rl0;
        float x1 = oacc[nj][2] * rl1, y1 = oacc[nj][3] * rl1;
        uint32_t h0 = pack_hi(x0, y0);
        uint32_t h1 = pack_hi(x1, y1);
        *(uint32_t*)(Ahb + (size_t)r0 * H_ + colb)       = h0;
        *(uint32_t*)(Ahb + (size_t)(r0 + 8) * H_ + colb) = h1;
        *(uint32_t*)(Alb + (size_t)r0 * H_ + colb)       = pack_lo(x0, y0, h0);
        *(uint32_t*)(Alb + (size_t)(r0 + 8) * H_ + colb) = pack_lo(x1, y1, h1);
    }
}

// ---------------------------------------------------------------------------
// Launch order puts qkv_hl at index 5 so the ncu capture (-s 5 -c 1) lands
// on it: [convQ, convK, convV, convW(q,k), convW(v,o), qkv, attn, gemm_o].
// ---------------------------------------------------------------------------
extern "C" void kernel_launch(void* const* d_in, const int* in_sizes, int n_in,
                              void* d_out, int out_size)
{
    const float* query = (const float*)d_in[0];
    const float* key   = (const float*)d_in[1];
    const float* value = (const float*)d_in[2];
    const int*   mask  = (const int*)d_in[3];

    const int wb = (n_in >= 13) ? 5 : 4;
    const float* Wq = (const float*)d_in[wb + 0];
    const float* bq = (const float*)d_in[wb + 1];
    const float* Wk = (const float*)d_in[wb + 2];
    const float* bk = (const float*)d_in[wb + 3];
    const float* Wv = (const float*)d_in[wb + 4];
    const float* bv = (const float*)d_in[wb + 5];
    const float* Wo = (const float*)d_in[wb + 6];
    const float* bo = (const float*)d_in[wb + 7];
    float* out = (float*)d_out;

    __nv_bfloat16 *xqh, *xql, *xkh, *xkl, *xvh, *xvl;
    __nv_bfloat16 *wqh, *wql, *wkh, *wkl, *wvh, *wvl, *woh, *wol;
    cudaGetSymbolAddress((void**)&xqh, g_xqh); cudaGetSymbolAddress((void**)&xql, g_xql);
    cudaGetSymbolAddress((void**)&xkh, g_xkh); cudaGetSymbolAddress((void**)&xkl, g_xkl);
    cudaGetSymbolAddress((void**)&xvh, g_xvh); cudaGetSymbolAddress((void**)&xvl, g_xvl);
    cudaGetSymbolAddress((void**)&wqh, g_wqh); cudaGetSymbolAddress((void**)&wql, g_wql);
    cudaGetSymbolAddress((void**)&wkh, g_wkh); cudaGetSymbolAddress((void**)&wkl, g_wkl);
    cudaGetSymbolAddress((void**)&wvh, g_wvh); cudaGetSymbolAddress((void**)&wvl, g_wvl);
    cudaGetSymbolAddress((void**)&woh, g_woh); cudaGetSymbolAddress((void**)&wol, g_wol);

    cudaFuncSetAttribute(qkv_hl,    cudaFuncAttributeMaxDynamicSharedMemorySize, GEMM_SMEM);
    cudaFuncSetAttribute(gemm_o_hl, cudaFuncAttributeMaxDynamicSharedMemorySize, GEMM_SMEM);
    cudaFuncSetAttribute(attn_tc,   cudaFuncAttributeMaxDynamicSharedMemorySize, ATTN_SMEM);

    const int nBig16 = NBIG / 16;      // 512K chunks
    const int nWt16  = H_ * H_ / 16;   // 64K
    conv_hl<<<2048, 256>>>(query, xqh, xql, nBig16);                     // 0
    conv_hl<<<2048, 256>>>(key,   xkh, xkl, nBig16);                     // 1
    conv_hl<<<2048, 256>>>(value, xvh, xvl, nBig16);                     // 2
    conv_hl2<<<dim3(256, 2), 256>>>(Wq, wqh, wql, Wk, wkh, wkl, nWt16);  // 3
    conv_hl2<<<dim3(256, 2), 256>>>(Wv, wvh, wvl, Wo, woh, wol, nWt16);  // 4

    dim3 qkvgrid(H_ / 128, MROWS / 128, 3);  // (8, 64, 3)
    qkv_hl<<<qkvgrid, 256, GEMM_SMEM>>>(bq, bk, bv);                     // 5 <- profiled

    dim3 agrid(S_ / 128, NH_, B_);           // (8, 16, 8)
    attn_tc<<<agrid, 256, ATTN_SMEM>>>(mask);                            // 6

    dim3 ggrid(H_ / 128, MROWS / 128);       // (8, 64)
    gemm_o_hl<<<ggrid, 256, GEMM_SMEM>>>(bo, out);                       // 7
}

// round 13
// speedup vs baseline: 1.0980x; 1.0980x over previous
#include <cuda_runtime.h>
#include <cuda_bf16.h>
#include <cstdint>

#define B_  8
#define S_  1024
#define H_  1024
#define NH_ 16
#define HD_ 64
#define MROWS (B_ * S_)
#define NBIG (MROWS * H_)

// Pre-converted input activations (hi/lo bf16)
__device__ __nv_bfloat16 g_xqh[NBIG], g_xql[NBIG];
__device__ __nv_bfloat16 g_xkh[NBIG], g_xkl[NBIG];
__device__ __nv_bfloat16 g_xvh[NBIG], g_xvl[NBIG];
// Projections (written split by qkv GEMM, consumed by attention)
__device__ __nv_bfloat16 g_qh[NBIG], g_ql[NBIG];
__device__ __nv_bfloat16 g_kh[NBIG], g_kl[NBIG];
__device__ __nv_bfloat16 g_vh[NBIG], g_vl[NBIG];
// Attention output (written split by attention, consumed by O GEMM)
__device__ __nv_bfloat16 g_ah[NBIG], g_al[NBIG];
// Weights (hi/lo)
__device__ __nv_bfloat16 g_wqh[H_ * H_], g_wql[H_ * H_];
__device__ __nv_bfloat16 g_wkh[H_ * H_], g_wkl[H_ * H_];
__device__ __nv_bfloat16 g_wvh[H_ * H_], g_wvl[H_ * H_];
__device__ __nv_bfloat16 g_woh[H_ * H_], g_wol[H_ * H_];

__device__ __forceinline__ uint32_t smem_u32(const void* p) {
    uint32_t a;
    asm("{ .reg .u64 t; cvta.to.shared.u64 t, %1; cvt.u32.u64 %0, t; }"
        : "=r"(a) : "l"(p));
    return a;
}

#define LDMX4(r0, r1, r2, r3, addr) \
    asm volatile("ldmatrix.sync.aligned.m8n8.x4.shared.b16 {%0,%1,%2,%3}, [%4];" \
                 : "=r"(r0), "=r"(r1), "=r"(r2), "=r"(r3) : "r"(addr))

#define LDMX4T(r0, r1, r2, r3, addr) \
    asm volatile("ldmatrix.sync.aligned.m8n8.x4.trans.shared.b16 {%0,%1,%2,%3}, [%4];" \
                 : "=r"(r0), "=r"(r1), "=r"(r2), "=r"(r3) : "r"(addr))

#define MMA16816(d, a, b) \
    asm volatile("mma.sync.aligned.m16n8k16.row.col.f32.bf16.bf16.f32 " \
                 "{%0,%1,%2,%3}, {%4,%5,%6,%7}, {%8,%9}, {%0,%1,%2,%3};" \
                 : "+f"((d)[0]), "+f"((d)[1]), "+f"((d)[2]), "+f"((d)[3]) \
                 : "r"((a)[0]), "r"((a)[1]), "r"((a)[2]), "r"((a)[3]), \
                   "r"((b)[0]), "r"((b)[1]))

#define CPA16(dst, src) \
    asm volatile("cp.async.cg.shared.global [%0], [%1], 16;" :: "r"(dst), "l"(src))
#define CP_COMMIT() asm volatile("cp.async.commit_group;")
#define CP_WAIT(n)  asm volatile("cp.async.wait_group %0;" :: "n"(n))

__device__ __forceinline__ uint32_t pack_hi(float x, float y) {
    __nv_bfloat162 h = __float22bfloat162_rn(make_float2(x, y));
    return *(uint32_t*)&h;
}
__device__ __forceinline__ uint32_t pack_lo(float x, float y, uint32_t hi) {
    __nv_bfloat162 h = *(__nv_bfloat162*)&hi;
    __nv_bfloat162 l = __float22bfloat162_rn(make_float2(
        x - __bfloat162float(h.x), y - __bfloat162float(h.y)));
    return *(uint32_t*)&l;
}

// ===========================================================================
// fp32 -> bf16 hi/lo split converts (R12 conv_chunk, passing).
// ===========================================================================
__device__ __forceinline__ void conv_chunk(
    const float* __restrict__ src, __nv_bfloat16* __restrict__ hi,
    __nv_bfloat16* __restrict__ lo, int i)
{
    float4 a = ((const float4*)src)[4 * i];
    float4 b = ((const float4*)src)[4 * i + 1];
    float4 c = ((const float4*)src)[4 * i + 2];
    float4 d = ((const float4*)src)[4 * i + 3];
    uint32_t h0 = pack_hi(a.x, a.y), h1 = pack_hi(a.z, a.w);
    uint32_t h2 = pack_hi(b.x, b.y), h3 = pack_hi(b.z, b.w);
    uint32_t h4 = pack_hi(c.x, c.y), h5 = pack_hi(c.z, c.w);
    uint32_t h6 = pack_hi(d.x, d.y), h7 = pack_hi(d.z, d.w);
    ((uint4*)hi)[2 * i]     = make_uint4(h0, h1, h2, h3);
    ((uint4*)hi)[2 * i + 1] = make_uint4(h4, h5, h6, h7);
    uint4 lo0 = make_uint4(pack_lo(a.x, a.y, h0), pack_lo(a.z, a.w, h1),
                           pack_lo(b.x, b.y, h2), pack_lo(b.z, b.w, h3));
    uint4 lo1 = make_uint4(pack_lo(c.x, c.y, h4), pack_lo(c.z, c.w, h5),
                           pack_lo(d.x, d.y, h6), pack_lo(d.z, d.w, h7));
    ((uint4*)lo)[2 * i]     = lo0;
    ((uint4*)lo)[2 * i + 1] = lo1;
}

__global__ __launch_bounds__(256)
void conv_hl(const float* __restrict__ src, __nv_bfloat16* __restrict__ hi,
             __nv_bfloat16* __restrict__ lo, int n16)
{
    for (int i = blockIdx.x * blockDim.x + threadIdx.x; i < n16;
         i += gridDim.x * blockDim.x)
        conv_chunk(src, hi, lo, i);
}

// All four weight matrices in one launch (blockIdx.y selects).
__global__ __launch_bounds__(256)
void conv_w4(const float* __restrict__ s0, const float* __restrict__ s1,
             const float* __restrict__ s2, const float* __restrict__ s3,
             int n16)
{
    const float* srcs[4] = { s0, s1, s2, s3 };
    __nv_bfloat16* his[4] = { g_wqh, g_wkh, g_wvh, g_woh };
    __nv_bfloat16* los[4] = { g_wql, g_wkl, g_wvl, g_wol };
    const float* src = srcs[blockIdx.y];
    __nv_bfloat16* hi = his[blockIdx.y];
    __nv_bfloat16* lo = los[blockIdx.y];
    for (int i = blockIdx.x * blockDim.x + threadIdx.x; i < n16;
         i += gridDim.x * blockDim.x)
        conv_chunk(src, hi, lo, i);
}

// ===========================================================================
// Pre-converted bf16 hi/lo GEMM. 128x128 tile, BK=64, 3-stage cp.async
// pipeline, ONE barrier per chunk, swizzled 128B rows (no padding).
// Swizzle: byte ^ ((byte>>3)&0x70); since row&7 == lane&7 for all fragment
// rows, it reduces to XORing column bits with (lane&7)<<4.
// ===========================================================================
#define HLTILE_B  (128 * 128)           // 16384 B per operand tile
#define HLSTAGE_B (4 * HLTILE_B)        // 65536 B (Ah, Al, Wh, Wl)
#define GEMM_SMEM (3 * HLSTAGE_B)       // 196608 B

__device__ __forceinline__ void hl_issue(
    uint32_t stage, const __nv_bfloat16* Ah, const __nv_bfloat16* Al,
    const __nv_bfloat16* Wh, const __nv_bfloat16* Wl, int k0, int tid)
{
    const __nv_bfloat16* srcs[4] = { Ah, Al, Wh, Wl };
#pragma unroll
    for (int t = 0; t < 4; t++) {
        const uint32_t db = stage + t * HLTILE_B;
        const __nv_bfloat16* sb = srcs[t] + k0;
#pragma unroll
        for (int j = 0; j < 4; j++) {
            const int idx = tid + j * 256;
            const int row = idx >> 3;
            const int c   = idx & 7;
            const uint32_t dst = db + row * 128 + ((c * 16) ^ ((row & 7) << 4));
            CPA16(dst, sb + (size_t)row * H_ + c * 8);
        }
    }
}

template<int SPLIT>
__device__ __forceinline__ void gemm_hl_body(
    const __nv_bfloat16* __restrict__ Ah, const __nv_bfloat16* __restrict__ Al,
    const __nv_bfloat16* __restrict__ Wh, const __nv_bfloat16* __restrict__ Wl,
    const float* __restrict__ bias, float* __restrict__ C,
    __nv_bfloat16* __restrict__ Ch, __nv_bfloat16* __restrict__ Cl,
    char* gsm, int bm0, int bn0)
{
    const int tid  = threadIdx.x;
    const int wid  = tid >> 5;
    const int lane = tid & 31;
    const int wm   = wid & 1;
    const int wn   = wid >> 1;

    const uint32_t ubase = smem_u32(gsm);
    const uint32_t lswz  = (uint32_t)((lane & 7) << 4);
    // A fragment: row = wm*64 + mi*16 + (lane&15); col = (lane>>4)*16 + ks*32
    const uint32_t aRow0 = (uint32_t)((wm * 64 + (lane & 15)) * 128);
    const uint32_t aCol  = ((uint32_t)((lane >> 4) * 16)) ^ lswz;
    // W fragment: row = wn*32 + pr*16 + ((lane>>4)&1)*8 + (lane&7); col = ((lane>>3)&1)*16 + ks*32
    const uint32_t wRow0 = (uint32_t)((wn * 32 + ((lane >> 4) & 1) * 8 + (lane & 7)) * 128);
    const uint32_t wCol  = ((uint32_t)(((lane >> 3) & 1) * 16)) ^ lswz;

    const __nv_bfloat16* At_h = Ah + (size_t)bm0 * H_;
    const __nv_bfloat16* At_l = Al + (size_t)bm0 * H_;
    const __nv_bfloat16* Wt_h = Wh + (size_t)bn0 * H_;
    const __nv_bfloat16* Wt_l = Wl + (size_t)bn0 * H_;

    float acc[4][4][4];
#pragma unroll
    for (int mi = 0; mi < 4; mi++)
#pragma unroll
        for (int nj = 0; nj < 4; nj++)
#pragma unroll
            for (int e = 0; e < 4; e++) acc[mi][nj][e] = 0.f;

    // prologue: stages 0, 1
    hl_issue(ubase,             At_h, At_l, Wt_h, Wt_l, 0,  tid);
    CP_COMMIT();
    hl_issue(ubase + HLSTAGE_B, At_h, At_l, Wt_h, Wt_l, 64, tid);
    CP_COMMIT();

    for (int c = 0; c < 16; c++) {
        if (c < 15) CP_WAIT(1); else CP_WAIT(0);
        __syncthreads();
        // issue stage c+2 into slot (c+2)%3 — its previous readers (chunk c-1)
        // all passed the barrier above, so no second barrier is needed.
        if (c < 14) {
            hl_issue(ubase + (uint32_t)((c + 2) % 3) * HLSTAGE_B,
                     At_h, At_l, Wt_h, Wt_l, (c + 2) * 64, tid);
            CP_COMMIT();
        }

        const uint32_t ub  = ubase + (uint32_t)(c % 3) * HLSTAGE_B;
        const uint32_t bAh = ub;
        const uint32_t bAl = ub + HLTILE_B;
        const uint32_t bWh = ub + 2 * HLTILE_B;
        const uint32_t bWl = ub + 3 * HLTILE_B;

#pragma unroll
        for (int ks = 0; ks < 4; ks++) {
            const uint32_t kA = (aCol ^ (uint32_t)(ks * 32));
            const uint32_t kW = (wCol ^ (uint32_t)(ks * 32));
            uint32_t ah[4][4], al[4][4];
#pragma unroll
            for (int mi = 0; mi < 4; mi++) {
                const uint32_t rowb = aRow0 + (uint32_t)(mi * 16 * 128) + kA;
                LDMX4(ah[mi][0], ah[mi][1], ah[mi][2], ah[mi][3], bAh + rowb);
                LDMX4(al[mi][0], al[mi][1], al[mi][2], al[mi][3], bAl + rowb);
            }
            uint32_t bh[4][2], bl[4][2];
#pragma unroll
            for (int pr = 0; pr < 2; pr++) {
                const uint32_t rowb = wRow0 + (uint32_t)(pr * 16 * 128) + kW;
                LDMX4(bh[pr * 2][0], bh[pr * 2][1], bh[pr * 2 + 1][0], bh[pr * 2 + 1][1], bWh + rowb);
                LDMX4(bl[pr * 2][0], bl[pr * 2][1], bl[pr * 2 + 1][0], bl[pr * 2 + 1][1], bWl + rowb);
            }
#pragma unroll
            for (int mi = 0; mi < 4; mi++)
#pragma unroll
                for (int nj = 0; nj < 4; nj++) {
                    MMA16816(acc[mi][nj], ah[mi], bh[nj]);
                    MMA16816(acc[mi][nj], al[mi], bh[nj]);
                    MMA16816(acc[mi][nj], ah[mi], bl[nj]);
                }
        }
    }

#pragma unroll
    for (int mi = 0; mi < 4; mi++) {
        const int r0 = bm0 + wm * 64 + mi * 16 + (lane >> 2);
#pragma unroll
        for (int nj = 0; nj < 4; nj++) {
            const int col = bn0 + wn * 32 + nj * 8 + (lane & 3) * 2;
            const float b0 = bias[col], b1 = bias[col + 1];
            float o0x = acc[mi][nj][0] + b0, o0y = acc[mi][nj][1] + b1;
            float o1x = acc[mi][nj][2] + b0, o1y = acc[mi][nj][3] + b1;
            if (SPLIT) {
                uint32_t h0 = pack_hi(o0x, o0y);
                uint32_t h1 = pack_hi(o1x, o1y);
                *(uint32_t*)(Ch + (size_t)r0 * H_ + col)       = h0;
                *(uint32_t*)(Ch + (size_t)(r0 + 8) * H_ + col) = h1;
                *(uint32_t*)(Cl + (size_t)r0 * H_ + col)       = pack_lo(o0x, o0y, h0);
                *(uint32_t*)(Cl + (size_t)(r0 + 8) * H_ + col) = pack_lo(o1x, o1y, h1);
            } else {
                *(float2*)(C + (size_t)r0 * H_ + col)       = make_float2(o0x, o0y);
                *(float2*)(C + (size_t)(r0 + 8) * H_ + col) = make_float2(o1x, o1y);
            }
        }
    }
}

// Fused Q/K/V projections: split bf16 outputs.
__global__ __launch_bounds__(256, 1)
void qkv_hl(const float* __restrict__ bq, const float* __restrict__ bk,
            const float* __restrict__ bv)
{
    extern __shared__ char gsm[];
    const __nv_bfloat16 *Ah, *Al, *Wh, *Wl;
    const float* bias;
    __nv_bfloat16 *Ch, *Cl;
    if (blockIdx.z == 0)      { Ah = g_xqh; Al = g_xql; Wh = g_wqh; Wl = g_wql; bias = bq; Ch = g_qh; Cl = g_ql; }
    else if (blockIdx.z == 1) { Ah = g_xkh; Al = g_xkl; Wh = g_wkh; Wl = g_wkl; bias = bk; Ch = g_kh; Cl = g_kl; }
    else                      { Ah = g_xvh; Al = g_xvl; Wh = g_wvh; Wl = g_wvl; bias = bv; Ch = g_vh; Cl = g_vl; }
    gemm_hl_body<1>(Ah, Al, Wh, Wl, bias, nullptr, Ch, Cl, gsm,
                    blockIdx.y * 128, blockIdx.x * 128);
}

__global__ __launch_bounds__(256, 1)
void gemm_o_hl(const float* __restrict__ bias, float* __restrict__ C)
{
    extern __shared__ char gsm[];
    gemm_hl_body<0>(g_ah, g_al, g_woh, g_wol, bias, C, nullptr, nullptr, gsm,
                    blockIdx.y * 128, blockIdx.x * 128);
}

// ===========================================================================
// Tensor-core flash attention on pre-split K/V (R12-exact, passing).
// ===========================================================================
#define AT_TILE_B  (64 * 144)
#define AT_STAGE_B (4 * AT_TILE_B)
#define ATTN_SMEM  (2 * AT_STAGE_B)

__device__ __forceinline__ void attn_issue(
    uint32_t stage, const __nv_bfloat16* Kh, const __nv_bfloat16* Kl,
    const __nv_bfloat16* Vh, const __nv_bfloat16* Vl, int tid)
{
    const __nv_bfloat16* srcs[4] = { Kh, Kl, Vh, Vl };
#pragma unroll
    for (int t = 0; t < 4; t++) {
        const uint32_t db = stage + t * AT_TILE_B;
        const __nv_bfloat16* sb = srcs[t];
#pragma unroll
        for (int j = 0; j < 2; j++) {
            const int idx = tid + j * 256;
            const int row = idx >> 3;
            const int c   = idx & 7;
            CPA16(db + row * 144 + c * 16, sb + (size_t)row * H_ + c * 8);
        }
    }
}

__global__ __launch_bounds__(256, 1)
void attn_tc(const int* __restrict__ mask)
{
    extern __shared__ char asmem[];
    __shared__ uint32_t s_mb[32];

    const int tid  = threadIdx.x;
    const int wid  = tid >> 5;
    const int lane = tid & 31;
    const int qt = blockIdx.x;
    const int h  = blockIdx.y;
    const int b  = blockIdx.z;

    const uint32_t ubase = smem_u32(asmem);

    const int r0 = wid * 16 + (lane >> 2);
    const size_t qoff = ((size_t)(b * S_ + qt * 128)) * H_ + h * HD_;
    const __nv_bfloat16* Qhb = g_qh + qoff;
    const __nv_bfloat16* Qlb = g_ql + qoff;
    uint32_t qh[4][4], ql[4][4];
#pragma unroll
    for (int ks = 0; ks < 4; ks++) {
        const int kb = ks * 16 + (lane & 3) * 2;
        qh[ks][0] = *(const uint32_t*)(Qhb + (size_t)r0 * H_ + kb);
        qh[ks][1] = *(const uint32_t*)(Qhb + (size_t)(r0 + 8) * H_ + kb);
        qh[ks][2] = *(const uint32_t*)(Qhb + (size_t)r0 * H_ + kb + 8);
        qh[ks][3] = *(const uint32_t*)(Qhb + (size_t)(r0 + 8) * H_ + kb + 8);
        ql[ks][0] = *(const uint32_t*)(Qlb + (size_t)r0 * H_ + kb);
        ql[ks][1] = *(const uint32_t*)(Qlb + (size_t)(r0 + 8) * H_ + kb);
        ql[ks][2] = *(const uint32_t*)(Qlb + (size_t)r0 * H_ + kb + 8);
        ql[ks][3] = *(const uint32_t*)(Qlb + (size_t)(r0 + 8) * H_ + kb + 8);
    }

    {
        int mv[4];
#pragma unroll
        for (int j = 0; j < 4; j++)
            mv[j] = mask[(size_t)b * S_ + (wid * 4 + j) * 32 + lane];
#pragma unroll
        for (int j = 0; j < 4; j++) {
            unsigned bv = __ballot_sync(0xffffffffu, mv[j] != 0);
            if (lane == 0) s_mb[wid * 4 + j] = bv;
        }
    }

    float oacc[8][4];
#pragma unroll
    for (int nj = 0; nj < 8; nj++)
#pragma unroll
        for (int e = 0; e < 4; e++) oacc[nj][e] = 0.f;
    float m0 = -1e30f, m1 = -1e30f, l0 = 0.f, l1 = 0.f;

    const size_t koff = (size_t)b * S_ * H_ + h * HD_;
    const __nv_bfloat16* Khb = g_kh + koff;
    const __nv_bfloat16* Klb = g_kl + koff;
    const __nv_bfloat16* Vhb = g_vh + koff;
    const __nv_bfloat16* Vlb = g_vl + koff;

    attn_issue(ubase, Khb, Klb, Vhb, Vlb, tid);
    CP_COMMIT();

    for (int kt = 0; kt < 16; kt++) {
        const int sel = kt & 1;
        CP_WAIT(0);
        __syncthreads();
        if (kt < 15) {
            const size_t toff = (size_t)(kt + 1) * 64 * H_;
            attn_issue(ubase + (uint32_t)(sel ^ 1) * AT_STAGE_B,
                       Khb + toff, Klb + toff, Vhb + toff, Vlb + toff, tid);
            CP_COMMIT();
        }
        const uint32_t mw0 = s_mb[2 * kt];
        const uint32_t mw1 = s_mb[2 * kt + 1];
        const uint32_t ub  = ubase + (uint32_t)sel * AT_STAGE_B;
        const uint32_t bKh = ub;
        const uint32_t bKl = ub + AT_TILE_B;
        const uint32_t bVh = ub + 2 * AT_TILE_B;
        const uint32_t bVl = ub + 3 * AT_TILE_B;

        float sacc[8][4];
#pragma unroll
        for (int nj = 0; nj < 8; nj++)
#pragma unroll
            for (int e = 0; e < 4; e++) sacc[nj][e] = 0.f;

#pragma unroll
        for (int ks = 0; ks < 4; ks++) {
            uint32_t bh[8][2], bl[8][2];
#pragma unroll
            for (int g = 0; g < 4; g++) {
                const uint32_t rowb =
                    (uint32_t)((g * 16 + ((lane >> 4) & 1) * 8 + (lane & 7)) * 144
                               + ks * 32 + ((lane >> 3) & 1) * 16);
                LDMX4(bh[2 * g][0], bh[2 * g][1], bh[2 * g + 1][0], bh[2 * g + 1][1], bKh + rowb);
                LDMX4(bl[2 * g][0], bl[2 * g][1], bl[2 * g + 1][0], bl[2 * g + 1][1], bKl + rowb);
            }
#pragma unroll
            for (int nj = 0; nj < 8; nj++) {
                MMA16816(sacc[nj], qh[ks], bh[nj]);
                MMA16816(sacc[nj], ql[ks], bh[nj]);
                MMA16816(sacc[nj], qh[ks], bl[nj]);
            }
        }

        const int shb = (lane & 3) * 2;
        float mx0 = -1e30f, mx1 = -1e30f;
#pragma unroll
        for (int nj = 0; nj < 8; nj++) {
            const uint32_t w = (nj < 4) ? mw0 : mw1;
            const int sh = (nj & 3) * 8 + shb;
            const bool k0 = (w >> sh) & 1;
            const bool k1 = (w >> (sh + 1)) & 1;
            float s0 = k0 ? -1e30f : sacc[nj][0] * 0.03125f;
            float s1 = k1 ? -1e30f : sacc[nj][1] * 0.03125f;
            float s2 = k0 ? -1e30f : sacc[nj][2] * 0.03125f;
            float s3 = k1 ? -1e30f : sacc[nj][3] * 0.03125f;
            sacc[nj][0] = s0; sacc[nj][1] = s1; sacc[nj][2] = s2; sacc[nj][3] = s3;
            mx0 = fmaxf(mx0, fmaxf(s0, s1));
            mx1 = fmaxf(mx1, fmaxf(s2, s3));
        }
        mx0 = fmaxf(mx0, __shfl_xor_sync(0xffffffffu, mx0, 1));
        mx0 = fmaxf(mx0, __shfl_xor_sync(0xffffffffu, mx0, 2));
        mx1 = fmaxf(mx1, __shfl_xor_sync(0xffffffffu, mx1, 1));
        mx1 = fmaxf(mx1, __shfl_xor_sync(0xffffffffu, mx1, 2));

        const float nm0 = fmaxf(m0, mx0);
        const float nm1 = fmaxf(m1, mx1);
        const float f0 = __expf(m0 - nm0);
        const float f1 = __expf(m1 - nm1);
        m0 = nm0; m1 = nm1;
        l0 *= f0;  l1 *= f1;
#pragma unroll
        for (int nj = 0; nj < 8; nj++) {
            oacc[nj][0] *= f0; oacc[nj][1] *= f0;
            oacc[nj][2] *= f1; oacc[nj][3] *= f1;
        }

        uint32_t pHa[8], pHb[8], pLa[8], pLb[8];
        float ps0 = 0.f, ps1 = 0.f;
#pragma unroll
        for (int nj = 0; nj < 8; nj++) {
            float p0 = __expf(sacc[nj][0] - nm0);
            float p1 = __expf(sacc[nj][1] - nm0);
            float p2 = __expf(sacc[nj][2] - nm1);
            float p3 = __expf(sacc[nj][3] - nm1);
            ps0 += p0 + p1;
            ps1 += p2 + p3;
            pHa[nj] = pack_hi(p0, p1);  pLa[nj] = pack_lo(p0, p1, pHa[nj]);
            pHb[nj] = pack_hi(p2, p3);  pLb[nj] = pack_lo(p2, p3, pHb[nj]);
        }
        l0 += ps0;
        l1 += ps1;

#pragma unroll
        for (int kk = 0; kk < 4; kk++) {
            uint32_t aH[4] = { pHa[2 * kk], pHb[2 * kk], pHa[2 * kk + 1], pHb[2 * kk + 1] };
            uint32_t aL[4] = { pLa[2 * kk], pLb[2 * kk], pLa[2 * kk + 1], pLb[2 * kk + 1] };
#pragma unroll
            for (int njp = 0; njp < 8; njp += 2) {
                const uint32_t rowb =
                    (uint32_t)((kk * 16 + (lane & 15)) * 144
                               + (njp + ((lane >> 4) & 1)) * 16);
                uint32_t vh[2][2], vl[2][2];
                LDMX4T(vh[0][0], vh[0][1], vh[1][0], vh[1][1], bVh + rowb);
                LDMX4T(vl[0][0], vl[0][1], vl[1][0], vl[1][1], bVl + rowb);
                MMA16816(oacc[njp],     aH, vh[0]);
                MMA16816(oacc[njp],     aL, vh[0]);
                MMA16816(oacc[njp],     aH, vl[0]);
                MMA16816(oacc[njp + 1], aH, vh[1]);
                MMA16816(oacc[njp + 1], aL, vh[1]);
                MMA16816(oacc[njp + 1], aH, vl[1]);
            }
        }
    }

    l0 += __shfl_xor_sync(0xffffffffu, l0, 1);
    l0 += __shfl_xor_sync(0xffffffffu, l0, 2);
    l1 += __shfl_xor_sync(0xffffffffu, l1, 1);
    l1 += __shfl_xor_sync(0xffffffffu, l1, 2);
    const float rl0 = 1.f / l0;
    const float rl1 = 1.f / l1;

    __nv_bfloat16* Ahb = g_ah + qoff;
    __nv_bfloat16* Alb = g_al + qoff;
#pragma unroll
    for (int nj = 0; nj < 8; nj++) {
        const int colb = nj * 8 + (lane & 3) * 2;
        float x0 = oacc[nj][0] * rl0, y0 = oacc[nj][1] * rl0;
        float x1 = oacc[nj][2] * rl1, y1 = oacc[nj][3] * rl1;
        uint32_t h0 = pack_hi(x0, y0);
        uint32_t h1 = pack_hi(x1, y1);
        *(uint32_t*)(Ahb + (size_t)r0 * H_ + colb)       = h0;
        *(uint32_t*)(Ahb + (size_t)(r0 + 8) * H_ + colb) = h1;
        *(uint32_t*)(Alb + (size_t)r0 * H_ + colb)       = pack_lo(x0, y0, h0);
        *(uint32_t*)(Alb + (size_t)(r0 + 8) * H_ + colb) = pack_lo(x1, y1, h1);
    }
}

// ---------------------------------------------------------------------------
// Launch order: the ncu capture lands on the 5th launch (0-based index 4),
// so qkv_hl is placed there:
// [convQ, convK, convV, convW4, qkv, attn, gemm_o]
// ---------------------------------------------------------------------------
extern "C" void kernel_launch(void* const* d_in, const int* in_sizes, int n_in,
                              void* d_out, int out_size)
{
    const float* query = (const float*)d_in[0];
    const float* key   = (const float*)d_in[1];
    const float* value = (const float*)d_in[2];
    const int*   mask  = (const int*)d_in[3];

    const int wb = (n_in >= 13) ? 5 : 4;
    const float* Wq = (const float*)d_in[wb + 0];
    const float* bq = (const float*)d_in[wb + 1];
    const float* Wk = (const float*)d_in[wb + 2];
    const float* bk = (const float*)d_in[wb + 3];
    const float* Wv = (const float*)d_in[wb + 4];
    const float* bv = (const float*)d_in[wb + 5];
    const float* Wo = (const float*)d_in[wb + 6];
    const float* bo = (const float*)d_in[wb + 7];
    float* out = (float*)d_out;

    __nv_bfloat16 *xqh, *xql, *xkh, *xkl, *xvh, *xvl;
    cudaGetSymbolAddress((void**)&xqh, g_xqh); cudaGetSymbolAddress((void**)&xql, g_xql);
    cudaGetSymbolAddress((void**)&xkh, g_xkh); cudaGetSymbolAddress((void**)&xkl, g_xkl);
    cudaGetSymbolAddress((void**)&xvh, g_xvh); cudaGetSymbolAddress((void**)&xvl, g_xvl);

    cudaFuncSetAttribute(qkv_hl,    cudaFuncAttributeMaxDynamicSharedMemorySize, GEMM_SMEM);
    cudaFuncSetAttribute(gemm_o_hl, cudaFuncAttributeMaxDynamicSharedMemorySize, GEMM_SMEM);
    cudaFuncSetAttribute(attn_tc,   cudaFuncAttributeMaxDynamicSharedMemorySize, ATTN_SMEM);

    const int nBig16 = NBIG / 16;
    const int nWt16  = H_ * H_ / 16;
    conv_hl<<<2048, 256>>>(query, xqh, xql, nBig16);            // 0
    conv_hl<<<2048, 256>>>(key,   xkh, xkl, nBig16);            // 1
    conv_hl<<<2048, 256>>>(value, xvh, xvl, nBig16);            // 2
    conv_w4<<<dim3(128, 4), 256>>>(Wq, Wk, Wv, Wo, nWt16);      // 3

    dim3 qkvgrid(H_ / 128, MROWS / 128, 3);  // (8, 64, 3)
    qkv_hl<<<qkvgrid, 256, GEMM_SMEM>>>(bq, bk, bv);            // 4 <- profiled

    dim3 agrid(S_ / 128, NH_, B_);           // (8, 16, 8)
    attn_tc<<<agrid, 256, ATTN_SMEM>>>(mask);                   // 5

    dim3 ggrid(H_ / 128, MROWS / 128);       // (8, 64)
    gemm_o_hl<<<ggrid, 256, GEMM_SMEM>>>(bo, out);              // 6
}

// round 14
// speedup vs baseline: 1.1264x; 1.0259x over previous
#include <cuda_runtime.h>
#include <cuda_bf16.h>
#include <cstdint>

#define B_  8
#define S_  1024
#define H_  1024
#define NH_ 16
#define HD_ 64
#define MROWS (B_ * S_)
#define NBIG (MROWS * H_)

// Pre-converted input activations (hi/lo bf16)
__device__ __nv_bfloat16 g_xqh[NBIG], g_xql[NBIG];
__device__ __nv_bfloat16 g_xkh[NBIG], g_xkl[NBIG];
__device__ __nv_bfloat16 g_xvh[NBIG], g_xvl[NBIG];
// Projections (written split by qkv GEMM, consumed by attention)
__device__ __nv_bfloat16 g_qh[NBIG], g_ql[NBIG];
__device__ __nv_bfloat16 g_kh[NBIG], g_kl[NBIG];
__device__ __nv_bfloat16 g_vh[NBIG], g_vl[NBIG];
// Attention output (written split by attention, consumed by O GEMM)
__device__ __nv_bfloat16 g_ah[NBIG], g_al[NBIG];
// Weights (hi/lo)
__device__ __nv_bfloat16 g_wqh[H_ * H_], g_wql[H_ * H_];
__device__ __nv_bfloat16 g_wkh[H_ * H_], g_wkl[H_ * H_];
__device__ __nv_bfloat16 g_wvh[H_ * H_], g_wvl[H_ * H_];
__device__ __nv_bfloat16 g_woh[H_ * H_], g_wol[H_ * H_];

__device__ __forceinline__ uint32_t smem_u32(const void* p) {
    uint32_t a;
    asm("{ .reg .u64 t; cvta.to.shared.u64 t, %1; cvt.u32.u64 %0, t; }"
        : "=r"(a) : "l"(p));
    return a;
}

#define LDMX4(r0, r1, r2, r3, addr) \
    asm volatile("ldmatrix.sync.aligned.m8n8.x4.shared.b16 {%0,%1,%2,%3}, [%4];" \
                 : "=r"(r0), "=r"(r1), "=r"(r2), "=r"(r3) : "r"(addr))

#define LDMX4T(r0, r1, r2, r3, addr) \
    asm volatile("ldmatrix.sync.aligned.m8n8.x4.trans.shared.b16 {%0,%1,%2,%3}, [%4];" \
                 : "=r"(r0), "=r"(r1), "=r"(r2), "=r"(r3) : "r"(addr))

#define MMA16816(d, a, b) \
    asm volatile("mma.sync.aligned.m16n8k16.row.col.f32.bf16.bf16.f32 " \
                 "{%0,%1,%2,%3}, {%4,%5,%6,%7}, {%8,%9}, {%0,%1,%2,%3};" \
                 : "+f"((d)[0]), "+f"((d)[1]), "+f"((d)[2]), "+f"((d)[3]) \
                 : "r"((a)[0]), "r"((a)[1]), "r"((a)[2]), "r"((a)[3]), \
                   "r"((b)[0]), "r"((b)[1]))

#define CPA16(dst, src) \
    asm volatile("cp.async.cg.shared.global [%0], [%1], 16;" :: "r"(dst), "l"(src))
#define CP_COMMIT() asm volatile("cp.async.commit_group;")
#define CP_WAIT(n)  asm volatile("cp.async.wait_group %0;" :: "n"(n))

__device__ __forceinline__ uint32_t pack_hi(float x, float y) {
    __nv_bfloat162 h = __float22bfloat162_rn(make_float2(x, y));
    return *(uint32_t*)&h;
}
__device__ __forceinline__ uint32_t pack_lo(float x, float y, uint32_t hi) {
    __nv_bfloat162 h = *(__nv_bfloat162*)&hi;
    __nv_bfloat162 l = __float22bfloat162_rn(make_float2(
        x - __bfloat162float(h.x), y - __bfloat162float(h.y)));
    return *(uint32_t*)&l;
}

// ===========================================================================
// fp32 -> bf16 hi/lo split converts (R13-exact).
// ===========================================================================
__device__ __forceinline__ void conv_chunk(
    const float* __restrict__ src, __nv_bfloat16* __restrict__ hi,
    __nv_bfloat16* __restrict__ lo, int i)
{
    float4 a = ((const float4*)src)[4 * i];
    float4 b = ((const float4*)src)[4 * i + 1];
    float4 c = ((const float4*)src)[4 * i + 2];
    float4 d = ((const float4*)src)[4 * i + 3];
    uint32_t h0 = pack_hi(a.x, a.y), h1 = pack_hi(a.z, a.w);
    uint32_t h2 = pack_hi(b.x, b.y), h3 = pack_hi(b.z, b.w);
    uint32_t h4 = pack_hi(c.x, c.y), h5 = pack_hi(c.z, c.w);
    uint32_t h6 = pack_hi(d.x, d.y), h7 = pack_hi(d.z, d.w);
    ((uint4*)hi)[2 * i]     = make_uint4(h0, h1, h2, h3);
    ((uint4*)hi)[2 * i + 1] = make_uint4(h4, h5, h6, h7);
    uint4 lo0 = make_uint4(pack_lo(a.x, a.y, h0), pack_lo(a.z, a.w, h1),
                           pack_lo(b.x, b.y, h2), pack_lo(b.z, b.w, h3));
    uint4 lo1 = make_uint4(pack_lo(c.x, c.y, h4), pack_lo(c.z, c.w, h5),
                           pack_lo(d.x, d.y, h6), pack_lo(d.z, d.w, h7));
    ((uint4*)lo)[2 * i]     = lo0;
    ((uint4*)lo)[2 * i + 1] = lo1;
}

__global__ __launch_bounds__(256)
void conv_hl(const float* __restrict__ src, __nv_bfloat16* __restrict__ hi,
             __nv_bfloat16* __restrict__ lo, int n16)
{
    for (int i = blockIdx.x * blockDim.x + threadIdx.x; i < n16;
         i += gridDim.x * blockDim.x)
        conv_chunk(src, hi, lo, i);
}

__global__ __launch_bounds__(256)
void conv_w4(const float* __restrict__ s0, const float* __restrict__ s1,
             const float* __restrict__ s2, const float* __restrict__ s3,
             int n16)
{
    const float* srcs[4] = { s0, s1, s2, s3 };
    __nv_bfloat16* his[4] = { g_wqh, g_wkh, g_wvh, g_woh };
    __nv_bfloat16* los[4] = { g_wql, g_wkl, g_wvl, g_wol };
    const float* src = srcs[blockIdx.y];
    __nv_bfloat16* hi = his[blockIdx.y];
    __nv_bfloat16* lo = los[blockIdx.y];
    for (int i = blockIdx.x * blockDim.x + threadIdx.x; i < n16;
         i += gridDim.x * blockDim.x)
        conv_chunk(src, hi, lo, i);
}

// ===========================================================================
// bf16 hi/lo GEMM (R13-exact, WIN). 3-stage, one barrier/chunk, swizzled.
// ===========================================================================
#define HLTILE_B  (128 * 128)
#define HLSTAGE_B (4 * HLTILE_B)
#define GEMM_SMEM (3 * HLSTAGE_B)       // 196608 B

__device__ __forceinline__ void hl_issue(
    uint32_t stage, const __nv_bfloat16* Ah, const __nv_bfloat16* Al,
    const __nv_bfloat16* Wh, const __nv_bfloat16* Wl, int k0, int tid)
{
    const __nv_bfloat16* srcs[4] = { Ah, Al, Wh, Wl };
#pragma unroll
    for (int t = 0; t < 4; t++) {
        const uint32_t db = stage + t * HLTILE_B;
        const __nv_bfloat16* sb = srcs[t] + k0;
#pragma unroll
        for (int j = 0; j < 4; j++) {
            const int idx = tid + j * 256;
            const int row = idx >> 3;
            const int c   = idx & 7;
            const uint32_t dst = db + row * 128 + ((c * 16) ^ ((row & 7) << 4));
            CPA16(dst, sb + (size_t)row * H_ + c * 8);
        }
    }
}

template<int SPLIT>
__device__ __forceinline__ void gemm_hl_body(
    const __nv_bfloat16* __restrict__ Ah, const __nv_bfloat16* __restrict__ Al,
    const __nv_bfloat16* __restrict__ Wh, const __nv_bfloat16* __restrict__ Wl,
    const float* __restrict__ bias, float* __restrict__ C,
    __nv_bfloat16* __restrict__ Ch, __nv_bfloat16* __restrict__ Cl,
    char* gsm, int bm0, int bn0)
{
    const int tid  = threadIdx.x;
    const int wid  = tid >> 5;
    const int lane = tid & 31;
    const int wm   = wid & 1;
    const int wn   = wid >> 1;

    const uint32_t ubase = smem_u32(gsm);
    const uint32_t lswz  = (uint32_t)((lane & 7) << 4);
    const uint32_t aRow0 = (uint32_t)((wm * 64 + (lane & 15)) * 128);
    const uint32_t aCol  = ((uint32_t)((lane >> 4) * 16)) ^ lswz;
    const uint32_t wRow0 = (uint32_t)((wn * 32 + ((lane >> 4) & 1) * 8 + (lane & 7)) * 128);
    const uint32_t wCol  = ((uint32_t)(((lane >> 3) & 1) * 16)) ^ lswz;

    const __nv_bfloat16* At_h = Ah + (size_t)bm0 * H_;
    const __nv_bfloat16* At_l = Al + (size_t)bm0 * H_;
    const __nv_bfloat16* Wt_h = Wh + (size_t)bn0 * H_;
    const __nv_bfloat16* Wt_l = Wl + (size_t)bn0 * H_;

    float acc[4][4][4];
#pragma unroll
    for (int mi = 0; mi < 4; mi++)
#pragma unroll
        for (int nj = 0; nj < 4; nj++)
#pragma unroll
            for (int e = 0; e < 4; e++) acc[mi][nj][e] = 0.f;

    hl_issue(ubase,             At_h, At_l, Wt_h, Wt_l, 0,  tid);
    CP_COMMIT();
    hl_issue(ubase + HLSTAGE_B, At_h, At_l, Wt_h, Wt_l, 64, tid);
    CP_COMMIT();

    for (int c = 0; c < 16; c++) {
        if (c < 15) CP_WAIT(1); else CP_WAIT(0);
        __syncthreads();
        if (c < 14) {
            hl_issue(ubase + (uint32_t)((c + 2) % 3) * HLSTAGE_B,
                     At_h, At_l, Wt_h, Wt_l, (c + 2) * 64, tid);
            CP_COMMIT();
        }

        const uint32_t ub  = ubase + (uint32_t)(c % 3) * HLSTAGE_B;
        const uint32_t bAh = ub;
        const uint32_t bAl = ub + HLTILE_B;
        const uint32_t bWh = ub + 2 * HLTILE_B;
        const uint32_t bWl = ub + 3 * HLTILE_B;

#pragma unroll
        for (int ks = 0; ks < 4; ks++) {
            const uint32_t kA = (aCol ^ (uint32_t)(ks * 32));
            const uint32_t kW = (wCol ^ (uint32_t)(ks * 32));
            uint32_t ah[4][4], al[4][4];
#pragma unroll
            for (int mi = 0; mi < 4; mi++) {
                const uint32_t rowb = aRow0 + (uint32_t)(mi * 16 * 128) + kA;
                LDMX4(ah[mi][0], ah[mi][1], ah[mi][2], ah[mi][3], bAh + rowb);
                LDMX4(al[mi][0], al[mi][1], al[mi][2], al[mi][3], bAl + rowb);
            }
            uint32_t bh[4][2], bl[4][2];
#pragma unroll
            for (int pr = 0; pr < 2; pr++) {
                const uint32_t rowb = wRow0 + (uint32_t)(pr * 16 * 128) + kW;
                LDMX4(bh[pr * 2][0], bh[pr * 2][1], bh[pr * 2 + 1][0], bh[pr * 2 + 1][1], bWh + rowb);
                LDMX4(bl[pr * 2][0], bl[pr * 2][1], bl[pr * 2 + 1][0], bl[pr * 2 + 1][1], bWl + rowb);
            }
#pragma unroll
            for (int mi = 0; mi < 4; mi++)
#pragma unroll
                for (int nj = 0; nj < 4; nj++) {
                    MMA16816(acc[mi][nj], ah[mi], bh[nj]);
                    MMA16816(acc[mi][nj], al[mi], bh[nj]);
                    MMA16816(acc[mi][nj], ah[mi], bl[nj]);
                }
        }
    }

#pragma unroll
    for (int mi = 0; mi < 4; mi++) {
        const int r0 = bm0 + wm * 64 + mi * 16 + (lane >> 2);
#pragma unroll
        for (int nj = 0; nj < 4; nj++) {
            const int col = bn0 + wn * 32 + nj * 8 + (lane & 3) * 2;
            const float b0 = bias[col], b1 = bias[col + 1];
            float o0x = acc[mi][nj][0] + b0, o0y = acc[mi][nj][1] + b1;
            float o1x = acc[mi][nj][2] + b0, o1y = acc[mi][nj][3] + b1;
            if (SPLIT) {
                uint32_t h0 = pack_hi(o0x, o0y);
                uint32_t h1 = pack_hi(o1x, o1y);
                *(uint32_t*)(Ch + (size_t)r0 * H_ + col)       = h0;
                *(uint32_t*)(Ch + (size_t)(r0 + 8) * H_ + col) = h1;
                *(uint32_t*)(Cl + (size_t)r0 * H_ + col)       = pack_lo(o0x, o0y, h0);
                *(uint32_t*)(Cl + (size_t)(r0 + 8) * H_ + col) = pack_lo(o1x, o1y, h1);
            } else {
                *(float2*)(C + (size_t)r0 * H_ + col)       = make_float2(o0x, o0y);
                *(float2*)(C + (size_t)(r0 + 8) * H_ + col) = make_float2(o1x, o1y);
            }
        }
    }
}

__global__ __launch_bounds__(256, 1)
void qkv_hl(const float* __restrict__ bq, const float* __restrict__ bk,
            const float* __restrict__ bv)
{
    extern __shared__ char gsm[];
    const __nv_bfloat16 *Ah, *Al, *Wh, *Wl;
    const float* bias;
    __nv_bfloat16 *Ch, *Cl;
    if (blockIdx.z == 0)      { Ah = g_xqh; Al = g_xql; Wh = g_wqh; Wl = g_wql; bias = bq; Ch = g_qh; Cl = g_ql; }
    else if (blockIdx.z == 1) { Ah = g_xkh; Al = g_xkl; Wh = g_wkh; Wl = g_wkl; bias = bk; Ch = g_kh; Cl = g_kl; }
    else                      { Ah = g_xvh; Al = g_xvl; Wh = g_wvh; Wl = g_wvl; bias = bv; Ch = g_vh; Cl = g_vl; }
    gemm_hl_body<1>(Ah, Al, Wh, Wl, bias, nullptr, Ch, Cl, gsm,
                    blockIdx.y * 128, blockIdx.x * 128);
}

__global__ __launch_bounds__(256, 1)
void gemm_o_hl(const float* __restrict__ bias, float* __restrict__ C)
{
    extern __shared__ char gsm[];
    gemm_hl_body<0>(g_ah, g_al, g_woh, g_wol, bias, C, nullptr, nullptr, gsm,
                    blockIdx.y * 128, blockIdx.x * 128);
}

// ===========================================================================
// Tensor-core flash attention: 3-stage swizzled 128B-row K/V staging
// (same structure as the winning GEMM), one barrier per tile, CP_WAIT(1).
// ===========================================================================
#define AT_TILE_B  (64 * 128)           // 8192 B per operand tile
#define AT_STAGE_B (4 * AT_TILE_B)      // 32768 B
#define ATTN_SMEM  (3 * AT_STAGE_B)     // 98304 B

__device__ __forceinline__ void attn_issue(
    uint32_t stage, const __nv_bfloat16* Kh, const __nv_bfloat16* Kl,
    const __nv_bfloat16* Vh, const __nv_bfloat16* Vl, int tid)
{
    const __nv_bfloat16* srcs[4] = { Kh, Kl, Vh, Vl };
#pragma unroll
    for (int t = 0; t < 4; t++) {
        const uint32_t db = stage + t * AT_TILE_B;
        const __nv_bfloat16* sb = srcs[t];
#pragma unroll
        for (int j = 0; j < 2; j++) {
            const int idx = tid + j * 256;
            const int row = idx >> 3;
            const int c   = idx & 7;
            const uint32_t dst = db + row * 128 + ((c * 16) ^ ((row & 7) << 4));
            CPA16(dst, sb + (size_t)row * H_ + c * 8);
        }
    }
}

__global__ __launch_bounds__(256, 1)
void attn_tc(const int* __restrict__ mask)
{
    extern __shared__ char asmem[];
    __shared__ uint32_t s_mb[32];

    const int tid  = threadIdx.x;
    const int wid  = tid >> 5;
    const int lane = tid & 31;
    const int qt = blockIdx.x;
    const int h  = blockIdx.y;
    const int b  = blockIdx.z;

    const uint32_t ubase = smem_u32(asmem);
    const uint32_t lswz  = (uint32_t)((lane & 7) << 4);
    // K fragment: row = g*16 + ((lane>>4)&1)*8 + (lane&7)
    const uint32_t kRow0 = (uint32_t)((((lane >> 4) & 1) * 8 + (lane & 7)) * 128);
    const uint32_t kCol  = ((uint32_t)(((lane >> 3) & 1) * 16)) ^ lswz;
    // V fragment (trans): row = kk*16 + (lane&15)
    const uint32_t vRow0 = (uint32_t)((lane & 15) * 128);

    const int r0 = wid * 16 + (lane >> 2);
    const size_t qoff = ((size_t)(b * S_ + qt * 128)) * H_ + h * HD_;
    const __nv_bfloat16* Qhb = g_qh + qoff;
    const __nv_bfloat16* Qlb = g_ql + qoff;
    uint32_t qh[4][4], ql[4][4];
#pragma unroll
    for (int ks = 0; ks < 4; ks++) {
        const int kb = ks * 16 + (lane & 3) * 2;
        qh[ks][0] = *(const uint32_t*)(Qhb + (size_t)r0 * H_ + kb);
        qh[ks][1] = *(const uint32_t*)(Qhb + (size_t)(r0 + 8) * H_ + kb);
        qh[ks][2] = *(const uint32_t*)(Qhb + (size_t)r0 * H_ + kb + 8);
        qh[ks][3] = *(const uint32_t*)(Qhb + (size_t)(r0 + 8) * H_ + kb + 8);
        ql[ks][0] = *(const uint32_t*)(Qlb + (size_t)r0 * H_ + kb);
        ql[ks][1] = *(const uint32_t*)(Qlb + (size_t)(r0 + 8) * H_ + kb);
        ql[ks][2] = *(const uint32_t*)(Qlb + (size_t)r0 * H_ + kb + 8);
        ql[ks][3] = *(const uint32_t*)(Qlb + (size_t)(r0 + 8) * H_ + kb + 8);
    }

    {
        int mv[4];
#pragma unroll
        for (int j = 0; j < 4; j++)
            mv[j] = mask[(size_t)b * S_ + (wid * 4 + j) * 32 + lane];
#pragma unroll
        for (int j = 0; j < 4; j++) {
            unsigned bv = __ballot_sync(0xffffffffu, mv[j] != 0);
            if (lane == 0) s_mb[wid * 4 + j] = bv;
        }
    }

    float oacc[8][4];
#pragma unroll
    for (int nj = 0; nj < 8; nj++)
#pragma unroll
        for (int e = 0; e < 4; e++) oacc[nj][e] = 0.f;
    float m0 = -1e30f, m1 = -1e30f, l0 = 0.f, l1 = 0.f;

    const size_t koff = (size_t)b * S_ * H_ + h * HD_;
    const __nv_bfloat16* Khb = g_kh + koff;
    const __nv_bfloat16* Klb = g_kl + koff;
    const __nv_bfloat16* Vhb = g_vh + koff;
    const __nv_bfloat16* Vlb = g_vl + koff;

    // prologue: stages 0, 1
    attn_issue(ubase,              Khb, Klb, Vhb, Vlb, tid);
    CP_COMMIT();
    attn_issue(ubase + AT_STAGE_B, Khb + (size_t)64 * H_, Klb + (size_t)64 * H_,
               Vhb + (size_t)64 * H_, Vlb + (size_t)64 * H_, tid);
    CP_COMMIT();

    for (int kt = 0; kt < 16; kt++) {
        if (kt < 15) CP_WAIT(1); else CP_WAIT(0);
        __syncthreads();
        if (kt < 14) {
            const size_t toff = (size_t)(kt + 2) * 64 * H_;
            attn_issue(ubase + (uint32_t)((kt + 2) % 3) * AT_STAGE_B,
                       Khb + toff, Klb + toff, Vhb + toff, Vlb + toff, tid);
            CP_COMMIT();
        }
        const uint32_t mw0 = s_mb[2 * kt];
        const uint32_t mw1 = s_mb[2 * kt + 1];
        const uint32_t ub  = ubase + (uint32_t)(kt % 3) * AT_STAGE_B;
        const uint32_t bKh = ub;
        const uint32_t bKl = ub + AT_TILE_B;
        const uint32_t bVh = ub + 2 * AT_TILE_B;
        const uint32_t bVl = ub + 3 * AT_TILE_B;

        // ---- S = Q K^T ----
        float sacc[8][4];
#pragma unroll
        for (int nj = 0; nj < 8; nj++)
#pragma unroll
            for (int e = 0; e < 4; e++) sacc[nj][e] = 0.f;

#pragma unroll
        for (int ks = 0; ks < 4; ks++) {
            const uint32_t kC = kCol ^ (uint32_t)(ks * 32);
            uint32_t bh[8][2], bl[8][2];
#pragma unroll
            for (int g = 0; g < 4; g++) {
                const uint32_t rowb = kRow0 + (uint32_t)(g * 16 * 128) + kC;
                LDMX4(bh[2 * g][0], bh[2 * g][1], bh[2 * g + 1][0], bh[2 * g + 1][1], bKh + rowb);
                LDMX4(bl[2 * g][0], bl[2 * g][1], bl[2 * g + 1][0], bl[2 * g + 1][1], bKl + rowb);
            }
#pragma unroll
            for (int nj = 0; nj < 8; nj++) {
                MMA16816(sacc[nj], qh[ks], bh[nj]);
                MMA16816(sacc[nj], ql[ks], bh[nj]);
                MMA16816(sacc[nj], qh[ks], bl[nj]);
            }
        }

        // ---- per-tile softmax ----
        const int shb = (lane & 3) * 2;
        float mx0 = -1e30f, mx1 = -1e30f;
#pragma unroll
        for (int nj = 0; nj < 8; nj++) {
            const uint32_t w = (nj < 4) ? mw0 : mw1;
            const int sh = (nj & 3) * 8 + shb;
            const bool k0 = (w >> sh) & 1;
            const bool k1 = (w >> (sh + 1)) & 1;
            float s0 = k0 ? -1e30f : sacc[nj][0] * 0.03125f;
            float s1 = k1 ? -1e30f : sacc[nj][1] * 0.03125f;
            float s2 = k0 ? -1e30f : sacc[nj][2] * 0.03125f;
            float s3 = k1 ? -1e30f : sacc[nj][3] * 0.03125f;
            sacc[nj][0] = s0; sacc[nj][1] = s1; sacc[nj][2] = s2; sacc[nj][3] = s3;
            mx0 = fmaxf(mx0, fmaxf(s0, s1));
            mx1 = fmaxf(mx1, fmaxf(s2, s3));
        }
        mx0 = fmaxf(mx0, __shfl_xor_sync(0xffffffffu, mx0, 1));
        mx0 = fmaxf(mx0, __shfl_xor_sync(0xffffffffu, mx0, 2));
        mx1 = fmaxf(mx1, __shfl_xor_sync(0xffffffffu, mx1, 1));
        mx1 = fmaxf(mx1, __shfl_xor_sync(0xffffffffu, mx1, 2));

        const float nm0 = fmaxf(m0, mx0);
        const float nm1 = fmaxf(m1, mx1);
        const float f0 = __expf(m0 - nm0);
        const float f1 = __expf(m1 - nm1);
        m0 = nm0; m1 = nm1;
        l0 *= f0;  l1 *= f1;
#pragma unroll
        for (int nj = 0; nj < 8; nj++) {
            oacc[nj][0] *= f0; oacc[nj][1] *= f0;
            oacc[nj][2] *= f1; oacc[nj][3] *= f1;
        }

        uint32_t pHa[8], pHb[8], pLa[8], pLb[8];
        float ps0 = 0.f, ps1 = 0.f;
#pragma unroll
        for (int nj = 0; nj < 8; nj++) {
            float p0 = __expf(sacc[nj][0] - nm0);
            float p1 = __expf(sacc[nj][1] - nm0);
            float p2 = __expf(sacc[nj][2] - nm1);
            float p3 = __expf(sacc[nj][3] - nm1);
            ps0 += p0 + p1;
            ps1 += p2 + p3;
            pHa[nj] = pack_hi(p0, p1);  pLa[nj] = pack_lo(p0, p1, pHa[nj]);
            pHb[nj] = pack_hi(p2, p3);  pLb[nj] = pack_lo(p2, p3, pHb[nj]);
        }
        l0 += ps0;
        l1 += ps1;

        // ---- O += P V ----
#pragma unroll
        for (int kk = 0; kk < 4; kk++) {
            uint32_t aH[4] = { pHa[2 * kk], pHb[2 * kk], pHa[2 * kk + 1], pHb[2 * kk + 1] };
            uint32_t aL[4] = { pLa[2 * kk], pLb[2 * kk], pLa[2 * kk + 1], pLb[2 * kk + 1] };
#pragma unroll
            for (int njp = 0; njp < 8; njp += 2) {
                const uint32_t colb =
                    ((uint32_t)((njp + ((lane >> 4) & 1)) * 16)) ^ lswz;
                const uint32_t rowb = vRow0 + (uint32_t)(kk * 16 * 128) + colb;
                uint32_t vh[2][2], vl[2][2];
                LDMX4T(vh[0][0], vh[0][1], vh[1][0], vh[1][1], bVh + rowb);
                LDMX4T(vl[0][0], vl[0][1], vl[1][0], vl[1][1], bVl + rowb);
                MMA16816(oacc[njp],     aH, vh[0]);
                MMA16816(oacc[njp],     aL, vh[0]);
                MMA16816(oacc[njp],     aH, vl[0]);
                MMA16816(oacc[njp + 1], aH, vh[1]);
                MMA16816(oacc[njp + 1], aL, vh[1]);
                MMA16816(oacc[njp + 1], aH, vl[1]);
            }
        }
    }

    l0 += __shfl_xor_sync(0xffffffffu, l0, 1);
    l0 += __shfl_xor_sync(0xffffffffu, l0, 2);
    l1 += __shfl_xor_sync(0xffffffffu, l1, 1);
    l1 += __shfl_xor_sync(0xffffffffu, l1, 2);
    const float rl0 = 1.f / l0;
    const float rl1 = 1.f / l1;

    __nv_bfloat16* Ahb = g_ah + qoff;
    __nv_bfloat16* Alb = g_al + qoff;
#pragma unroll
    for (int nj = 0; nj < 8; nj++) {
        const int colb = nj * 8 + (lane & 3) * 2;
        float x0 = oacc[nj][0] * rl0, y0 = oacc[nj][1] * rl0;
        float x1 = oacc[nj][2] * rl1, y1 = oacc[nj][3] * rl1;
        uint32_t h0 = pack_hi(x0, y0);
        uint32_t h1 = pack_hi(x1, y1);
        *(uint32_t*)(Ahb + (size_t)r0 * H_ + colb)       = h0;
        *(uint32_t*)(Ahb + (size_t)(r0 + 8) * H_ + colb) = h1;
        *(uint32_t*)(Alb + (size_t)r0 * H_ + colb)       = pack_lo(x0, y0, h0);
        *(uint32_t*)(Alb + (size_t)(r0 + 8) * H_ + colb) = pack_lo(x1, y1, h1);
    }
}

// ---------------------------------------------------------------------------
extern "C" void kernel_launch(void* const* d_in, const int* in_sizes, int n_in,
                              void* d_out, int out_size)
{
    const float* query = (const float*)d_in[0];
    const float* key   = (const float*)d_in[1];
    const float* value = (const float*)d_in[2];
    const int*   mask  = (const int*)d_in[3];

    const int wb = (n_in >= 13) ? 5 : 4;
    const float* Wq = (const float*)d_in[wb + 0];
    const float* bq = (const float*)d_in[wb + 1];
    const float* Wk = (const float*)d_in[wb + 2];
    const float* bk = (const float*)d_in[wb + 3];
    const float* Wv = (const float*)d_in[wb + 4];
    const float* bv = (const float*)d_in[wb + 5];
    const float* Wo = (const float*)d_in[wb + 6];
    const float* bo = (const float*)d_in[wb + 7];
    float* out = (float*)d_out;

    __nv_bfloat16 *xqh, *xql, *xkh, *xkl, *xvh, *xvl;
    cudaGetSymbolAddress((void**)&xqh, g_xqh); cudaGetSymbolAddress((void**)&xql, g_xql);
    cudaGetSymbolAddress((void**)&xkh, g_xkh); cudaGetSymbolAddress((void**)&xkl, g_xkl);
    cudaGetSymbolAddress((void**)&xvh, g_xvh); cudaGetSymbolAddress((void**)&xvl, g_xvl);

    cudaFuncSetAttribute(qkv_hl,    cudaFuncAttributeMaxDynamicSharedMemorySize, GEMM_SMEM);
    cudaFuncSetAttribute(gemm_o_hl, cudaFuncAttributeMaxDynamicSharedMemorySize, GEMM_SMEM);
    cudaFuncSetAttribute(attn_tc,   cudaFuncAttributeMaxDynamicSharedMemorySize, ATTN_SMEM);

    const int nBig16 = NBIG / 16;
    const int nWt16  = H_ * H_ / 16;
    conv_hl<<<2048, 256>>>(query, xqh, xql, nBig16);            // 0
    conv_hl<<<2048, 256>>>(key,   xkh, xkl, nBig16);            // 1
    conv_hl<<<2048, 256>>>(value, xvh, xvl, nBig16);            // 2
    conv_w4<<<dim3(128, 4), 256>>>(Wq, Wk, Wv, Wo, nWt16);      // 3

    dim3 qkvgrid(H_ / 128, MROWS / 128, 3);  // (8, 64, 3)
    qkv_hl<<<qkvgrid, 256, GEMM_SMEM>>>(bq, bk, bv);            // 4

    dim3 agrid(S_ / 128, NH_, B_);           // (8, 16, 8)
    attn_tc<<<agrid, 256, ATTN_SMEM>>>(mask);                   // 5

    dim3 ggrid(H_ / 128, MROWS / 128);       // (8, 64)
    gemm_o_hl<<<ggrid, 256, GEMM_SMEM>>>(bo, out);              // 6
}

// round 15
// speedup vs baseline: 1.2045x; 1.0694x over previous
#include <cuda_runtime.h>
#include <cuda_bf16.h>
#include <cstdint>

#define B_  8
#define S_  1024
#define H_  1024
#define NH_ 16
#define HD_ 64
#define MROWS (B_ * S_)
#define NBIG (MROWS * H_)

// Pre-converted input activations (hi/lo bf16)
__device__ __nv_bfloat16 g_xqh[NBIG], g_xql[NBIG];
__device__ __nv_bfloat16 g_xkh[NBIG], g_xkl[NBIG];
__device__ __nv_bfloat16 g_xvh[NBIG], g_xvl[NBIG];
// Projections (written split by qkv GEMM, consumed by attention)
__device__ __nv_bfloat16 g_qh[NBIG], g_ql[NBIG];
__device__ __nv_bfloat16 g_kh[NBIG], g_kl[NBIG];
__device__ __nv_bfloat16 g_vh[NBIG], g_vl[NBIG];
// Attention output (written split by attention, consumed by O GEMM)
__device__ __nv_bfloat16 g_ah[NBIG], g_al[NBIG];
// Weights (hi/lo)
__device__ __nv_bfloat16 g_wqh[H_ * H_], g_wql[H_ * H_];
__device__ __nv_bfloat16 g_wkh[H_ * H_], g_wkl[H_ * H_];
__device__ __nv_bfloat16 g_wvh[H_ * H_], g_wvl[H_ * H_];
__device__ __nv_bfloat16 g_woh[H_ * H_], g_wol[H_ * H_];

__device__ __forceinline__ uint32_t smem_u32(const void* p) {
    uint32_t a;
    asm("{ .reg .u64 t; cvta.to.shared.u64 t, %1; cvt.u32.u64 %0, t; }"
        : "=r"(a) : "l"(p));
    return a;
}

#define LDMX4(r0, r1, r2, r3, addr) \
    asm volatile("ldmatrix.sync.aligned.m8n8.x4.shared.b16 {%0,%1,%2,%3}, [%4];" \
                 : "=r"(r0), "=r"(r1), "=r"(r2), "=r"(r3) : "r"(addr))

#define LDMX4T(r0, r1, r2, r3, addr) \
    asm volatile("ldmatrix.sync.aligned.m8n8.x4.trans.shared.b16 {%0,%1,%2,%3}, [%4];" \
                 : "=r"(r0), "=r"(r1), "=r"(r2), "=r"(r3) : "r"(addr))

#define MMA16816(d, a, b) \
    asm volatile("mma.sync.aligned.m16n8k16.row.col.f32.bf16.bf16.f32 " \
                 "{%0,%1,%2,%3}, {%4,%5,%6,%7}, {%8,%9}, {%0,%1,%2,%3};" \
                 : "+f"((d)[0]), "+f"((d)[1]), "+f"((d)[2]), "+f"((d)[3]) \
                 : "r"((a)[0]), "r"((a)[1]), "r"((a)[2]), "r"((a)[3]), \
                   "r"((b)[0]), "r"((b)[1]))

#define CPA16(dst, src) \
    asm volatile("cp.async.cg.shared.global [%0], [%1], 16;" :: "r"(dst), "l"(src))
#define CP_COMMIT() asm volatile("cp.async.commit_group;")
#define CP_WAIT(n)  asm volatile("cp.async.wait_group %0;" :: "n"(n))

__device__ __forceinline__ uint32_t pack_hi(float x, float y) {
    __nv_bfloat162 h = __float22bfloat162_rn(make_float2(x, y));
    return *(uint32_t*)&h;
}
__device__ __forceinline__ uint32_t pack_lo(float x, float y, uint32_t hi) {
    __nv_bfloat162 h = *(__nv_bfloat162*)&hi;
    __nv_bfloat162 l = __float22bfloat162_rn(make_float2(
        x - __bfloat162float(h.x), y - __bfloat162float(h.y)));
    return *(uint32_t*)&l;
}

// ===========================================================================
// fp32 -> bf16 hi/lo split converts (R13-exact).
// ===========================================================================
__device__ __forceinline__ void conv_chunk(
    const float* __restrict__ src, __nv_bfloat16* __restrict__ hi,
    __nv_bfloat16* __restrict__ lo, int i)
{
    float4 a = ((const float4*)src)[4 * i];
    float4 b = ((const float4*)src)[4 * i + 1];
    float4 c = ((const float4*)src)[4 * i + 2];
    float4 d = ((const float4*)src)[4 * i + 3];
    uint32_t h0 = pack_hi(a.x, a.y), h1 = pack_hi(a.z, a.w);
    uint32_t h2 = pack_hi(b.x, b.y), h3 = pack_hi(b.z, b.w);
    uint32_t h4 = pack_hi(c.x, c.y), h5 = pack_hi(c.z, c.w);
    uint32_t h6 = pack_hi(d.x, d.y), h7 = pack_hi(d.z, d.w);
    ((uint4*)hi)[2 * i]     = make_uint4(h0, h1, h2, h3);
    ((uint4*)hi)[2 * i + 1] = make_uint4(h4, h5, h6, h7);
    uint4 lo0 = make_uint4(pack_lo(a.x, a.y, h0), pack_lo(a.z, a.w, h1),
                           pack_lo(b.x, b.y, h2), pack_lo(b.z, b.w, h3));
    uint4 lo1 = make_uint4(pack_lo(c.x, c.y, h4), pack_lo(c.z, c.w, h5),
                           pack_lo(d.x, d.y, h6), pack_lo(d.z, d.w, h7));
    ((uint4*)lo)[2 * i]     = lo0;
    ((uint4*)lo)[2 * i + 1] = lo1;
}

__global__ __launch_bounds__(256)
void conv_hl(const float* __restrict__ src, __nv_bfloat16* __restrict__ hi,
             __nv_bfloat16* __restrict__ lo, int n16)
{
    for (int i = blockIdx.x * blockDim.x + threadIdx.x; i < n16;
         i += gridDim.x * blockDim.x)
        conv_chunk(src, hi, lo, i);
}

__global__ __launch_bounds__(256)
void conv_w4(const float* __restrict__ s0, const float* __restrict__ s1,
             const float* __restrict__ s2, const float* __restrict__ s3,
             int n16)
{
    const float* srcs[4] = { s0, s1, s2, s3 };
    __nv_bfloat16* his[4] = { g_wqh, g_wkh, g_wvh, g_woh };
    __nv_bfloat16* los[4] = { g_wql, g_wkl, g_wvl, g_wol };
    const float* src = srcs[blockIdx.y];
    __nv_bfloat16* hi = his[blockIdx.y];
    __nv_bfloat16* lo = los[blockIdx.y];
    for (int i = blockIdx.x * blockDim.x + threadIdx.x; i < n16;
         i += gridDim.x * blockDim.x)
        conv_chunk(src, hi, lo, i);
}

// ===========================================================================
// bf16 hi/lo GEMM, 64x128 tile, 128 threads (4 warps, 64x32 each), BK=64,
// 2-stage / one-barrier pipeline (wait(0) -> sync -> issue -> compute),
// swizzled 128B rows. 96KB smem -> 2 CTAs/SM.
// ===========================================================================
#define GA_TILE_B  (64 * 128)            // A operand tile: 8192 B
#define GW_TILE_B  (128 * 128)           // W operand tile: 16384 B
#define GSTAGE_B   (2 * GA_TILE_B + 2 * GW_TILE_B)  // 49152 B
#define GEMM_SMEM  (2 * GSTAGE_B)        // 98304 B

__device__ __forceinline__ void hl_issue(
    uint32_t stage, const __nv_bfloat16* Ah, const __nv_bfloat16* Al,
    const __nv_bfloat16* Wh, const __nv_bfloat16* Wl, int k0, int tid)
{
    // A tiles: 64 rows (4 iters of 128 threads), W tiles: 128 rows (8 iters).
    const __nv_bfloat16* aops[2] = { Ah, Al };
    const __nv_bfloat16* wops[2] = { Wh, Wl };
#pragma unroll
    for (int t = 0; t < 2; t++) {
        const uint32_t db = stage + t * GA_TILE_B;
        const __nv_bfloat16* sb = aops[t] + k0;
#pragma unroll
        for (int j = 0; j < 4; j++) {
            const int idx = tid + j * 128;
            const int row = idx >> 3;
            const int c   = idx & 7;
            const uint32_t dst = db + row * 128 + ((c * 16) ^ ((row & 7) << 4));
            CPA16(dst, sb + (size_t)row * H_ + c * 8);
        }
    }
#pragma unroll
    for (int t = 0; t < 2; t++) {
        const uint32_t db = stage + 2 * GA_TILE_B + t * GW_TILE_B;
        const __nv_bfloat16* sb = wops[t] + k0;
#pragma unroll
        for (int j = 0; j < 8; j++) {
            const int idx = tid + j * 128;
            const int row = idx >> 3;
            const int c   = idx & 7;
            const uint32_t dst = db + row * 128 + ((c * 16) ^ ((row & 7) << 4));
            CPA16(dst, sb + (size_t)row * H_ + c * 8);
        }
    }
}

template<int SPLIT>
__device__ __forceinline__ void gemm_hl_body(
    const __nv_bfloat16* __restrict__ Ah, const __nv_bfloat16* __restrict__ Al,
    const __nv_bfloat16* __restrict__ Wh, const __nv_bfloat16* __restrict__ Wl,
    const float* __restrict__ bias, float* __restrict__ C,
    __nv_bfloat16* __restrict__ Ch, __nv_bfloat16* __restrict__ Cl,
    char* gsm, int bm0, int bn0)
{
    const int tid  = threadIdx.x;
    const int wid  = tid >> 5;          // 0..3 = n-slice
    const int lane = tid & 31;

    const uint32_t ubase = smem_u32(gsm);
    const uint32_t lswz  = (uint32_t)((lane & 7) << 4);
    const uint32_t aRow0 = (uint32_t)((lane & 15) * 128);
    const uint32_t aCol  = ((uint32_t)((lane >> 4) * 16)) ^ lswz;
    const uint32_t wRow0 = (uint32_t)((wid * 32 + ((lane >> 4) & 1) * 8 + (lane & 7)) * 128);
    const uint32_t wCol  = ((uint32_t)(((lane >> 3) & 1) * 16)) ^ lswz;

    const __nv_bfloat16* At_h = Ah + (size_t)bm0 * H_;
    const __nv_bfloat16* At_l = Al + (size_t)bm0 * H_;
    const __nv_bfloat16* Wt_h = Wh + (size_t)bn0 * H_;
    const __nv_bfloat16* Wt_l = Wl + (size_t)bn0 * H_;

    float acc[4][4][4];
#pragma unroll
    for (int mi = 0; mi < 4; mi++)
#pragma unroll
        for (int nj = 0; nj < 4; nj++)
#pragma unroll
            for (int e = 0; e < 4; e++) acc[mi][nj][e] = 0.f;

    // prologue: stage 0
    hl_issue(ubase, At_h, At_l, Wt_h, Wt_l, 0, tid);
    CP_COMMIT();

    for (int c = 0; c < 16; c++) {
        CP_WAIT(0);
        __syncthreads();
        // issue c+1 into the other slot; its chunk c-1 readers passed the
        // barrier above, and it has the whole compute of chunk c to land.
        if (c < 15) {
            hl_issue(ubase + (uint32_t)((c + 1) & 1) * GSTAGE_B,
                     At_h, At_l, Wt_h, Wt_l, (c + 1) * 64, tid);
            CP_COMMIT();
        }

        const uint32_t ub  = ubase + (uint32_t)(c & 1) * GSTAGE_B;
        const uint32_t bAh = ub;
        const uint32_t bAl = ub + GA_TILE_B;
        const uint32_t bWh = ub + 2 * GA_TILE_B;
        const uint32_t bWl = ub + 2 * GA_TILE_B + GW_TILE_B;

#pragma unroll
        for (int ks = 0; ks < 4; ks++) {
            const uint32_t kA = (aCol ^ (uint32_t)(ks * 32));
            const uint32_t kW = (wCol ^ (uint32_t)(ks * 32));
            uint32_t ah[4][4], al[4][4];
#pragma unroll
            for (int mi = 0; mi < 4; mi++) {
                const uint32_t rowb = aRow0 + (uint32_t)(mi * 16 * 128) + kA;
                LDMX4(ah[mi][0], ah[mi][1], ah[mi][2], ah[mi][3], bAh + rowb);
                LDMX4(al[mi][0], al[mi][1], al[mi][2], al[mi][3], bAl + rowb);
            }
            uint32_t bh[4][2], bl[4][2];
#pragma unroll
            for (int pr = 0; pr < 2; pr++) {
                const uint32_t rowb = wRow0 + (uint32_t)(pr * 16 * 128) + kW;
                LDMX4(bh[pr * 2][0], bh[pr * 2][1], bh[pr * 2 + 1][0], bh[pr * 2 + 1][1], bWh + rowb);
                LDMX4(bl[pr * 2][0], bl[pr * 2][1], bl[pr * 2 + 1][0], bl[pr * 2 + 1][1], bWl + rowb);
            }
#pragma unroll
            for (int mi = 0; mi < 4; mi++)
#pragma unroll
                for (int nj = 0; nj < 4; nj++) {
                    MMA16816(acc[mi][nj], ah[mi], bh[nj]);
                    MMA16816(acc[mi][nj], al[mi], bh[nj]);
                    MMA16816(acc[mi][nj], ah[mi], bl[nj]);
                }
        }
    }

#pragma unroll
    for (int mi = 0; mi < 4; mi++) {
        const int r0 = bm0 + mi * 16 + (lane >> 2);
#pragma unroll
        for (int nj = 0; nj < 4; nj++) {
            const int col = bn0 + wid * 32 + nj * 8 + (lane & 3) * 2;
            const float b0 = bias[col], b1 = bias[col + 1];
            float o0x = acc[mi][nj][0] + b0, o0y = acc[mi][nj][1] + b1;
            float o1x = acc[mi][nj][2] + b0, o1y = acc[mi][nj][3] + b1;
            if (SPLIT) {
                uint32_t h0 = pack_hi(o0x, o0y);
                uint32_t h1 = pack_hi(o1x, o1y);
                *(uint32_t*)(Ch + (size_t)r0 * H_ + col)       = h0;
                *(uint32_t*)(Ch + (size_t)(r0 + 8) * H_ + col) = h1;
                *(uint32_t*)(Cl + (size_t)r0 * H_ + col)       = pack_lo(o0x, o0y, h0);
                *(uint32_t*)(Cl + (size_t)(r0 + 8) * H_ + col) = pack_lo(o1x, o1y, h1);
            } else {
                *(float2*)(C + (size_t)r0 * H_ + col)       = make_float2(o0x, o0y);
                *(float2*)(C + (size_t)(r0 + 8) * H_ + col) = make_float2(o1x, o1y);
            }
        }
    }
}

__global__ __launch_bounds__(128, 2)
void qkv_hl(const float* __restrict__ bq, const float* __restrict__ bk,
            const float* __restrict__ bv)
{
    extern __shared__ char gsm[];
    const __nv_bfloat16 *Ah, *Al, *Wh, *Wl;
    const float* bias;
    __nv_bfloat16 *Ch, *Cl;
    if (blockIdx.z == 0)      { Ah = g_xqh; Al = g_xql; Wh = g_wqh; Wl = g_wql; bias = bq; Ch = g_qh; Cl = g_ql; }
    else if (blockIdx.z == 1) { Ah = g_xkh; Al = g_xkl; Wh = g_wkh; Wl = g_wkl; bias = bk; Ch = g_kh; Cl = g_kl; }
    else                      { Ah = g_xvh; Al = g_xvl; Wh = g_wvh; Wl = g_wvl; bias = bv; Ch = g_vh; Cl = g_vl; }
    gemm_hl_body<1>(Ah, Al, Wh, Wl, bias, nullptr, Ch, Cl, gsm,
                    blockIdx.y * 64, blockIdx.x * 128);
}

__global__ __launch_bounds__(128, 2)
void gemm_o_hl(const float* __restrict__ bias, float* __restrict__ C)
{
    extern __shared__ char gsm[];
    gemm_hl_body<0>(g_ah, g_al, g_woh, g_wol, bias, C, nullptr, nullptr, gsm,
                    blockIdx.y * 64, blockIdx.x * 128);
}

// ===========================================================================
// Tensor-core flash attention (R14-exact, WIN): 3-stage swizzled 128B-row
// K/V staging, one barrier per tile, CP_WAIT(1).
// ===========================================================================
#define AT_TILE_B  (64 * 128)
#define AT_STAGE_B (4 * AT_TILE_B)
#define ATTN_SMEM  (3 * AT_STAGE_B)     // 98304 B

__device__ __forceinline__ void attn_issue(
    uint32_t stage, const __nv_bfloat16* Kh, const __nv_bfloat16* Kl,
    const __nv_bfloat16* Vh, const __nv_bfloat16* Vl, int tid)
{
    const __nv_bfloat16* srcs[4] = { Kh, Kl, Vh, Vl };
#pragma unroll
    for (int t = 0; t < 4; t++) {
        const uint32_t db = stage + t * AT_TILE_B;
        const __nv_bfloat16* sb = srcs[t];
#pragma unroll
        for (int j = 0; j < 2; j++) {
            const int idx = tid + j * 256;
            const int row = idx >> 3;
            const int c   = idx & 7;
            const uint32_t dst = db + row * 128 + ((c * 16) ^ ((row & 7) << 4));
            CPA16(dst, sb + (size_t)row * H_ + c * 8);
        }
    }
}

__global__ __launch_bounds__(256, 1)
void attn_tc(const int* __restrict__ mask)
{
    extern __shared__ char asmem[];
    __shared__ uint32_t s_mb[32];

    const int tid  = threadIdx.x;
    const int wid  = tid >> 5;
    const int lane = tid & 31;
    const int qt = blockIdx.x;
    const int h  = blockIdx.y;
    const int b  = blockIdx.z;

    const uint32_t ubase = smem_u32(asmem);
    const uint32_t lswz  = (uint32_t)((lane & 7) << 4);
    const uint32_t kRow0 = (uint32_t)((((lane >> 4) & 1) * 8 + (lane & 7)) * 128);
    const uint32_t kCol  = ((uint32_t)(((lane >> 3) & 1) * 16)) ^ lswz;
    const uint32_t vRow0 = (uint32_t)((lane & 15) * 128);

    const int r0 = wid * 16 + (lane >> 2);
    const size_t qoff = ((size_t)(b * S_ + qt * 128)) * H_ + h * HD_;
    const __nv_bfloat16* Qhb = g_qh + qoff;
    const __nv_bfloat16* Qlb = g_ql + qoff;
    uint32_t qh[4][4], ql[4][4];
#pragma unroll
    for (int ks = 0; ks < 4; ks++) {
        const int kb = ks * 16 + (lane & 3) * 2;
        qh[ks][0] = *(const uint32_t*)(Qhb + (size_t)r0 * H_ + kb);
        qh[ks][1] = *(const uint32_t*)(Qhb + (size_t)(r0 + 8) * H_ + kb);
        qh[ks][2] = *(const uint32_t*)(Qhb + (size_t)r0 * H_ + kb + 8);
        qh[ks][3] = *(const uint32_t*)(Qhb + (size_t)(r0 + 8) * H_ + kb + 8);
        ql[ks][0] = *(const uint32_t*)(Qlb + (size_t)r0 * H_ + kb);
        ql[ks][1] = *(const uint32_t*)(Qlb + (size_t)(r0 + 8) * H_ + kb);
        ql[ks][2] = *(const uint32_t*)(Qlb + (size_t)r0 * H_ + kb + 8);
        ql[ks][3] = *(const uint32_t*)(Qlb + (size_t)(r0 + 8) * H_ + kb + 8);
    }

    {
        int mv[4];
#pragma unroll
        for (int j = 0; j < 4; j++)
            mv[j] = mask[(size_t)b * S_ + (wid * 4 + j) * 32 + lane];
#pragma unroll
        for (int j = 0; j < 4; j++) {
            unsigned bv = __ballot_sync(0xffffffffu, mv[j] != 0);
            if (lane == 0) s_mb[wid * 4 + j] = bv;
        }
    }

    float oacc[8][4];
#pragma unroll
    for (int nj = 0; nj < 8; nj++)
#pragma unroll
        for (int e = 0; e < 4; e++) oacc[nj][e] = 0.f;
    float m0 = -1e30f, m1 = -1e30f, l0 = 0.f, l1 = 0.f;

    const size_t koff = (size_t)b * S_ * H_ + h * HD_;
    const __nv_bfloat16* Khb = g_kh + koff;
    const __nv_bfloat16* Klb = g_kl + koff;
    const __nv_bfloat16* Vhb = g_vh + koff;
    const __nv_bfloat16* Vlb = g_vl + koff;

    attn_issue(ubase,              Khb, Klb, Vhb, Vlb, tid);
    CP_COMMIT();
    attn_issue(ubase + AT_STAGE_B, Khb + (size_t)64 * H_, Klb + (size_t)64 * H_,
               Vhb + (size_t)64 * H_, Vlb + (size_t)64 * H_, tid);
    CP_COMMIT();

    for (int kt = 0; kt < 16; kt++) {
        if (kt < 15) CP_WAIT(1); else CP_WAIT(0);
        __syncthreads();
        if (kt < 14) {
            const size_t toff = (size_t)(kt + 2) * 64 * H_;
            attn_issue(ubase + (uint32_t)((kt + 2) % 3) * AT_STAGE_B,
                       Khb + toff, Klb + toff, Vhb + toff, Vlb + toff, tid);
            CP_COMMIT();
        }
        const uint32_t mw0 = s_mb[2 * kt];
        const uint32_t mw1 = s_mb[2 * kt + 1];
        const uint32_t ub  = ubase + (uint32_t)(kt % 3) * AT_STAGE_B;
        const uint32_t bKh = ub;
        const uint32_t bKl = ub + AT_TILE_B;
        const uint32_t bVh = ub + 2 * AT_TILE_B;
        const uint32_t bVl = ub + 3 * AT_TILE_B;

        float sacc[8][4];
#pragma unroll
        for (int nj = 0; nj < 8; nj++)
#pragma unroll
            for (int e = 0; e < 4; e++) sacc[nj][e] = 0.f;

#pragma unroll
        for (int ks = 0; ks < 4; ks++) {
            const uint32_t kC = kCol ^ (uint32_t)(ks * 32);
            uint32_t bh[8][2], bl[8][2];
#pragma unroll
            for (int g = 0; g < 4; g++) {
                const uint32_t rowb = kRow0 + (uint32_t)(g * 16 * 128) + kC;
                LDMX4(bh[2 * g][0], bh[2 * g][1], bh[2 * g + 1][0], bh[2 * g + 1][1], bKh + rowb);
                LDMX4(bl[2 * g][0], bl[2 * g][1], bl[2 * g + 1][0], bl[2 * g + 1][1], bKl + rowb);
            }
#pragma unroll
            for (int nj = 0; nj < 8; nj++) {
                MMA16816(sacc[nj], qh[ks], bh[nj]);
                MMA16816(sacc[nj], ql[ks], bh[nj]);
                MMA16816(sacc[nj], qh[ks], bl[nj]);
            }
        }

        const int shb = (lane & 3) * 2;
        float mx0 = -1e30f, mx1 = -1e30f;
#pragma unroll
        for (int nj = 0; nj < 8; nj++) {
            const uint32_t w = (nj < 4) ? mw0 : mw1;
            const int sh = (nj & 3) * 8 + shb;
            const bool k0 = (w >> sh) & 1;
            const bool k1 = (w >> (sh + 1)) & 1;
            float s0 = k0 ? -1e30f : sacc[nj][0] * 0.03125f;
            float s1 = k1 ? -1e30f : sacc[nj][1] * 0.03125f;
            float s2 = k0 ? -1e30f : sacc[nj][2] * 0.03125f;
            float s3 = k1 ? -1e30f : sacc[nj][3] * 0.03125f;
            sacc[nj][0] = s0; sacc[nj][1] = s1; sacc[nj][2] = s2; sacc[nj][3] = s3;
            mx0 = fmaxf(mx0, fmaxf(s0, s1));
            mx1 = fmaxf(mx1, fmaxf(s2, s3));
        }
        mx0 = fmaxf(mx0, __shfl_xor_sync(0xffffffffu, mx0, 1));
        mx0 = fmaxf(mx0, __shfl_xor_sync(0xffffffffu, mx0, 2));
        mx1 = fmaxf(mx1, __shfl_xor_sync(0xffffffffu, mx1, 1));
        mx1 = fmaxf(mx1, __shfl_xor_sync(0xffffffffu, mx1, 2));

        const float nm0 = fmaxf(m0, mx0);
        const float nm1 = fmaxf(m1, mx1);
        const float f0 = __expf(m0 - nm0);
        const float f1 = __expf(m1 - nm1);
        m0 = nm0; m1 = nm1;
        l0 *= f0;  l1 *= f1;
#pragma unroll
        for (int nj = 0; nj < 8; nj++) {
            oacc[nj][0] *= f0; oacc[nj][1] *= f0;
            oacc[nj][2] *= f1; oacc[nj][3] *= f1;
        }

        uint32_t pHa[8], pHb[8], pLa[8], pLb[8];
        float ps0 = 0.f, ps1 = 0.f;
#pragma unroll
        for (int nj = 0; nj < 8; nj++) {
            float p0 = __expf(sacc[nj][0] - nm0);
            float p1 = __expf(sacc[nj][1] - nm0);
            float p2 = __expf(sacc[nj][2] - nm1);
            float p3 = __expf(sacc[nj][3] - nm1);
            ps0 += p0 + p1;
            ps1 += p2 + p3;
            pHa[nj] = pack_hi(p0, p1);  pLa[nj] = pack_lo(p0, p1, pHa[nj]);
            pHb[nj] = pack_hi(p2, p3);  pLb[nj] = pack_lo(p2, p3, pHb[nj]);
        }
        l0 += ps0;
        l1 += ps1;

#pragma unroll
        for (int kk = 0; kk < 4; kk++) {
            uint32_t aH[4] = { pHa[2 * kk], pHb[2 * kk], pHa[2 * kk + 1], pHb[2 * kk + 1] };
            uint32_t aL[4] = { pLa[2 * kk], pLb[2 * kk], pLa[2 * kk + 1], pLb[2 * kk + 1] };
#pragma unroll
            for (int njp = 0; njp < 8; njp += 2) {
                const uint32_t colb =
                    ((uint32_t)((njp + ((lane >> 4) & 1)) * 16)) ^ lswz;
                const uint32_t rowb = vRow0 + (uint32_t)(kk * 16 * 128) + colb;
                uint32_t vh[2][2], vl[2][2];
                LDMX4T(vh[0][0], vh[0][1], vh[1][0], vh[1][1], bVh + rowb);
                LDMX4T(vl[0][0], vl[0][1], vl[1][0], vl[1][1], bVl + rowb);
                MMA16816(oacc[njp],     aH, vh[0]);
                MMA16816(oacc[njp],     aL, vh[0]);
                MMA16816(oacc[njp],     aH, vl[0]);
                MMA16816(oacc[njp + 1], aH, vh[1]);
                MMA16816(oacc[njp + 1], aL, vh[1]);
                MMA16816(oacc[njp + 1], aH, vl[1]);
            }
        }
    }

    l0 += __shfl_xor_sync(0xffffffffu, l0, 1);
    l0 += __shfl_xor_sync(0xffffffffu, l0, 2);
    l1 += __shfl_xor_sync(0xffffffffu, l1, 1);
    l1 += __shfl_xor_sync(0xffffffffu, l1, 2);
    const float rl0 = 1.f / l0;
    const float rl1 = 1.f / l1;

    __nv_bfloat16* Ahb = g_ah + qoff;
    __nv_bfloat16* Alb = g_al + qoff;
#pragma unroll
    for (int nj = 0; nj < 8; nj++) {
        const int colb = nj * 8 + (lane & 3) * 2;
        float x0 = oacc[nj][0] * rl0, y0 = oacc[nj][1] * rl0;
        float x1 = oacc[nj][2] * rl1, y1 = oacc[nj][3] * rl1;
        uint32_t h0 = pack_hi(x0, y0);
        uint32_t h1 = pack_hi(x1, y1);
        *(uint32_t*)(Ahb + (size_t)r0 * H_ + colb)       = h0;
        *(uint32_t*)(Ahb + (size_t)(r0 + 8) * H_ + colb) = h1;
        *(uint32_t*)(Alb + (size_t)r0 * H_ + colb)       = pack_lo(x0, y0, h0);
        *(uint32_t*)(Alb + (size_t)(r0 + 8) * H_ + colb) = pack_lo(x1, y1, h1);
    }
}

// ---------------------------------------------------------------------------
extern "C" void kernel_launch(void* const* d_in, const int* in_sizes, int n_in,
                              void* d_out, int out_size)
{
    const float* query = (const float*)d_in[0];
    const float* key   = (const float*)d_in[1];
    const float* value = (const float*)d_in[2];
    const int*   mask  = (const int*)d_in[3];

    const int wb = (n_in >= 13) ? 5 : 4;
    const float* Wq = (const float*)d_in[wb + 0];
    const float* bq = (const float*)d_in[wb + 1];
    const float* Wk = (const float*)d_in[wb + 2];
    const float* bk = (const float*)d_in[wb + 3];
    const float* Wv = (const float*)d_in[wb + 4];
    const float* bv = (const float*)d_in[wb + 5];
    const float* Wo = (const float*)d_in[wb + 6];
    const float* bo = (const float*)d_in[wb + 7];
    float* out = (float*)d_out;

    __nv_bfloat16 *xqh, *xql, *xkh, *xkl, *xvh, *xvl;
    cudaGetSymbolAddress((void**)&xqh, g_xqh); cudaGetSymbolAddress((void**)&xql, g_xql);
    cudaGetSymbolAddress((void**)&xkh, g_xkh); cudaGetSymbolAddress((void**)&xkl, g_xkl);
    cudaGetSymbolAddress((void**)&xvh, g_xvh); cudaGetSymbolAddress((void**)&xvl, g_xvl);

    cudaFuncSetAttribute(qkv_hl,    cudaFuncAttributeMaxDynamicSharedMemorySize, GEMM_SMEM);
    cudaFuncSetAttribute(gemm_o_hl, cudaFuncAttributeMaxDynamicSharedMemorySize, GEMM_SMEM);
    cudaFuncSetAttribute(attn_tc,   cudaFuncAttributeMaxDynamicSharedMemorySize, ATTN_SMEM);

    const int nBig16 = NBIG / 16;
    const int nWt16  = H_ * H_ / 16;
    conv_hl<<<2048, 256>>>(query, xqh, xql, nBig16);            // 0
    conv_hl<<<2048, 256>>>(key,   xkh, xkl, nBig16);            // 1
    conv_hl<<<2048, 256>>>(value, xvh, xvl, nBig16);            // 2
    conv_w4<<<dim3(128, 4), 256>>>(Wq, Wk, Wv, Wo, nWt16);      // 3

    dim3 qkvgrid(H_ / 128, MROWS / 64, 3);   // (8, 128, 3)
    qkv_hl<<<qkvgrid, 128, GEMM_SMEM>>>(bq, bk, bv);            // 4

    dim3 agrid(S_ / 128, NH_, B_);           // (8, 16, 8)
    attn_tc<<<agrid, 256, ATTN_SMEM>>>(mask);                   // 5

    dim3 ggrid(H_ / 128, MROWS / 64);        // (8, 128)
    gemm_o_hl<<<ggrid, 128, GEMM_SMEM>>>(bo, out);              // 6
}

// round 16
// speedup vs baseline: 1.2208x; 1.0135x over previous
#include <cuda_runtime.h>
#include <cuda_bf16.h>
#include <cstdint>

#define B_  8
#define S_  1024
#define H_  1024
#define NH_ 16
#define HD_ 64
#define MROWS (B_ * S_)
#define NBIG (MROWS * H_)

// Pre-converted input activations (hi/lo bf16)
__device__ __nv_bfloat16 g_xqh[NBIG], g_xql[NBIG];
__device__ __nv_bfloat16 g_xkh[NBIG], g_xkl[NBIG];
__device__ __nv_bfloat16 g_xvh[NBIG], g_xvl[NBIG];
// Projections (written split by qkv GEMM, consumed by attention)
__device__ __nv_bfloat16 g_qh[NBIG], g_ql[NBIG];
__device__ __nv_bfloat16 g_kh[NBIG], g_kl[NBIG];
__device__ __nv_bfloat16 g_vh[NBIG], g_vl[NBIG];
// Attention output (written split by attention, consumed by O GEMM)
__device__ __nv_bfloat16 g_ah[NBIG], g_al[NBIG];
// Weights (hi/lo)
__device__ __nv_bfloat16 g_wqh[H_ * H_], g_wql[H_ * H_];
__device__ __nv_bfloat16 g_wkh[H_ * H_], g_wkl[H_ * H_];
__device__ __nv_bfloat16 g_wvh[H_ * H_], g_wvl[H_ * H_];
__device__ __nv_bfloat16 g_woh[H_ * H_], g_wol[H_ * H_];

__device__ __forceinline__ uint32_t smem_u32(const void* p) {
    uint32_t a;
    asm("{ .reg .u64 t; cvta.to.shared.u64 t, %1; cvt.u32.u64 %0, t; }"
        : "=r"(a) : "l"(p));
    return a;
}

#define LDMX4(r0, r1, r2, r3, addr) \
    asm volatile("ldmatrix.sync.aligned.m8n8.x4.shared.b16 {%0,%1,%2,%3}, [%4];" \
                 : "=r"(r0), "=r"(r1), "=r"(r2), "=r"(r3) : "r"(addr))

#define LDMX4T(r0, r1, r2, r3, addr) \
    asm volatile("ldmatrix.sync.aligned.m8n8.x4.trans.shared.b16 {%0,%1,%2,%3}, [%4];" \
                 : "=r"(r0), "=r"(r1), "=r"(r2), "=r"(r3) : "r"(addr))

#define MMA16816(d, a, b) \
    asm volatile("mma.sync.aligned.m16n8k16.row.col.f32.bf16.bf16.f32 " \
                 "{%0,%1,%2,%3}, {%4,%5,%6,%7}, {%8,%9}, {%0,%1,%2,%3};" \
                 : "+f"((d)[0]), "+f"((d)[1]), "+f"((d)[2]), "+f"((d)[3]) \
                 : "r"((a)[0]), "r"((a)[1]), "r"((a)[2]), "r"((a)[3]), \
                   "r"((b)[0]), "r"((b)[1]))

#define CPA16(dst, src) \
    asm volatile("cp.async.cg.shared.global [%0], [%1], 16;" :: "r"(dst), "l"(src))
#define CP_COMMIT() asm volatile("cp.async.commit_group;")
#define CP_WAIT(n)  asm volatile("cp.async.wait_group %0;" :: "n"(n))

__device__ __forceinline__ uint32_t pack_hi(float x, float y) {
    __nv_bfloat162 h = __float22bfloat162_rn(make_float2(x, y));
    return *(uint32_t*)&h;
}
__device__ __forceinline__ uint32_t pack_lo(float x, float y, uint32_t hi) {
    __nv_bfloat162 h = *(__nv_bfloat162*)&hi;
    __nv_bfloat162 l = __float22bfloat162_rn(make_float2(
        x - __bfloat162float(h.x), y - __bfloat162float(h.y)));
    return *(uint32_t*)&l;
}

// ===========================================================================
// fp32 -> bf16 hi/lo split converts (R13-exact).
// ===========================================================================
__device__ __forceinline__ void conv_chunk(
    const float* __restrict__ src, __nv_bfloat16* __restrict__ hi,
    __nv_bfloat16* __restrict__ lo, int i)
{
    float4 a = ((const float4*)src)[4 * i];
    float4 b = ((const float4*)src)[4 * i + 1];
    float4 c = ((const float4*)src)[4 * i + 2];
    float4 d = ((const float4*)src)[4 * i + 3];
    uint32_t h0 = pack_hi(a.x, a.y), h1 = pack_hi(a.z, a.w);
    uint32_t h2 = pack_hi(b.x, b.y), h3 = pack_hi(b.z, b.w);
    uint32_t h4 = pack_hi(c.x, c.y), h5 = pack_hi(c.z, c.w);
    uint32_t h6 = pack_hi(d.x, d.y), h7 = pack_hi(d.z, d.w);
    ((uint4*)hi)[2 * i]     = make_uint4(h0, h1, h2, h3);
    ((uint4*)hi)[2 * i + 1] = make_uint4(h4, h5, h6, h7);
    uint4 lo0 = make_uint4(pack_lo(a.x, a.y, h0), pack_lo(a.z, a.w, h1),
                           pack_lo(b.x, b.y, h2), pack_lo(b.z, b.w, h3));
    uint4 lo1 = make_uint4(pack_lo(c.x, c.y, h4), pack_lo(c.z, c.w, h5),
                           pack_lo(d.x, d.y, h6), pack_lo(d.z, d.w, h7));
    ((uint4*)lo)[2 * i]     = lo0;
    ((uint4*)lo)[2 * i + 1] = lo1;
}

__global__ __launch_bounds__(256)
void conv_hl(const float* __restrict__ src, __nv_bfloat16* __restrict__ hi,
             __nv_bfloat16* __restrict__ lo, int n16)
{
    for (int i = blockIdx.x * blockDim.x + threadIdx.x; i < n16;
         i += gridDim.x * blockDim.x)
        conv_chunk(src, hi, lo, i);
}

__global__ __launch_bounds__(256)
void conv_w4(const float* __restrict__ s0, const float* __restrict__ s1,
             const float* __restrict__ s2, const float* __restrict__ s3,
             int n16)
{
    const float* srcs[4] = { s0, s1, s2, s3 };
    __nv_bfloat16* his[4] = { g_wqh, g_wkh, g_wvh, g_woh };
    __nv_bfloat16* los[4] = { g_wql, g_wkl, g_wvl, g_wol };
    const float* src = srcs[blockIdx.y];
    __nv_bfloat16* hi = his[blockIdx.y];
    __nv_bfloat16* lo = los[blockIdx.y];
    for (int i = blockIdx.x * blockDim.x + threadIdx.x; i < n16;
         i += gridDim.x * blockDim.x)
        conv_chunk(src, hi, lo, i);
}

// ===========================================================================
// bf16 hi/lo GEMM (R15-exact, WIN): 64x128 tile, 128 threads, 2-stage /
// one-barrier pipeline, swizzled 128B rows, 2 CTAs/SM.
// ===========================================================================
#define GA_TILE_B  (64 * 128)
#define GW_TILE_B  (128 * 128)
#define GSTAGE_B   (2 * GA_TILE_B + 2 * GW_TILE_B)  // 49152 B
#define GEMM_SMEM  (2 * GSTAGE_B)        // 98304 B

__device__ __forceinline__ void hl_issue(
    uint32_t stage, const __nv_bfloat16* Ah, const __nv_bfloat16* Al,
    const __nv_bfloat16* Wh, const __nv_bfloat16* Wl, int k0, int tid)
{
    const __nv_bfloat16* aops[2] = { Ah, Al };
    const __nv_bfloat16* wops[2] = { Wh, Wl };
#pragma unroll
    for (int t = 0; t < 2; t++) {
        const uint32_t db = stage + t * GA_TILE_B;
        const __nv_bfloat16* sb = aops[t] + k0;
#pragma unroll
        for (int j = 0; j < 4; j++) {
            const int idx = tid + j * 128;
            const int row = idx >> 3;
            const int c   = idx & 7;
            const uint32_t dst = db + row * 128 + ((c * 16) ^ ((row & 7) << 4));
            CPA16(dst, sb + (size_t)row * H_ + c * 8);
        }
    }
#pragma unroll
    for (int t = 0; t < 2; t++) {
        const uint32_t db = stage + 2 * GA_TILE_B + t * GW_TILE_B;
        const __nv_bfloat16* sb = wops[t] + k0;
#pragma unroll
        for (int j = 0; j < 8; j++) {
            const int idx = tid + j * 128;
            const int row = idx >> 3;
            const int c   = idx & 7;
            const uint32_t dst = db + row * 128 + ((c * 16) ^ ((row & 7) << 4));
            CPA16(dst, sb + (size_t)row * H_ + c * 8);
        }
    }
}

template<int SPLIT>
__device__ __forceinline__ void gemm_hl_body(
    const __nv_bfloat16* __restrict__ Ah, const __nv_bfloat16* __restrict__ Al,
    const __nv_bfloat16* __restrict__ Wh, const __nv_bfloat16* __restrict__ Wl,
    const float* __restrict__ bias, float* __restrict__ C,
    __nv_bfloat16* __restrict__ Ch, __nv_bfloat16* __restrict__ Cl,
    char* gsm, int bm0, int bn0)
{
    const int tid  = threadIdx.x;
    const int wid  = tid >> 5;
    const int lane = tid & 31;

    const uint32_t ubase = smem_u32(gsm);
    const uint32_t lswz  = (uint32_t)((lane & 7) << 4);
    const uint32_t aRow0 = (uint32_t)((lane & 15) * 128);
    const uint32_t aCol  = ((uint32_t)((lane >> 4) * 16)) ^ lswz;
    const uint32_t wRow0 = (uint32_t)((wid * 32 + ((lane >> 4) & 1) * 8 + (lane & 7)) * 128);
    const uint32_t wCol  = ((uint32_t)(((lane >> 3) & 1) * 16)) ^ lswz;

    const __nv_bfloat16* At_h = Ah + (size_t)bm0 * H_;
    const __nv_bfloat16* At_l = Al + (size_t)bm0 * H_;
    const __nv_bfloat16* Wt_h = Wh + (size_t)bn0 * H_;
    const __nv_bfloat16* Wt_l = Wl + (size_t)bn0 * H_;

    float acc[4][4][4];
#pragma unroll
    for (int mi = 0; mi < 4; mi++)
#pragma unroll
        for (int nj = 0; nj < 4; nj++)
#pragma unroll
            for (int e = 0; e < 4; e++) acc[mi][nj][e] = 0.f;

    hl_issue(ubase, At_h, At_l, Wt_h, Wt_l, 0, tid);
    CP_COMMIT();

    for (int c = 0; c < 16; c++) {
        CP_WAIT(0);
        __syncthreads();
        if (c < 15) {
            hl_issue(ubase + (uint32_t)((c + 1) & 1) * GSTAGE_B,
                     At_h, At_l, Wt_h, Wt_l, (c + 1) * 64, tid);
            CP_COMMIT();
        }

        const uint32_t ub  = ubase + (uint32_t)(c & 1) * GSTAGE_B;
        const uint32_t bAh = ub;
        const uint32_t bAl = ub + GA_TILE_B;
        const uint32_t bWh = ub + 2 * GA_TILE_B;
        const uint32_t bWl = ub + 2 * GA_TILE_B + GW_TILE_B;

#pragma unroll
        for (int ks = 0; ks < 4; ks++) {
            const uint32_t kA = (aCol ^ (uint32_t)(ks * 32));
            const uint32_t kW = (wCol ^ (uint32_t)(ks * 32));
            uint32_t ah[4][4], al[4][4];
#pragma unroll
            for (int mi = 0; mi < 4; mi++) {
                const uint32_t rowb = aRow0 + (uint32_t)(mi * 16 * 128) + kA;
                LDMX4(ah[mi][0], ah[mi][1], ah[mi][2], ah[mi][3], bAh + rowb);
                LDMX4(al[mi][0], al[mi][1], al[mi][2], al[mi][3], bAl + rowb);
            }
            uint32_t bh[4][2], bl[4][2];
#pragma unroll
            for (int pr = 0; pr < 2; pr++) {
                const uint32_t rowb = wRow0 + (uint32_t)(pr * 16 * 128) + kW;
                LDMX4(bh[pr * 2][0], bh[pr * 2][1], bh[pr * 2 + 1][0], bh[pr * 2 + 1][1], bWh + rowb);
                LDMX4(bl[pr * 2][0], bl[pr * 2][1], bl[pr * 2 + 1][0], bl[pr * 2 + 1][1], bWl + rowb);
            }
#pragma unroll
            for (int mi = 0; mi < 4; mi++)
#pragma unroll
                for (int nj = 0; nj < 4; nj++) {
                    MMA16816(acc[mi][nj], ah[mi], bh[nj]);
                    MMA16816(acc[mi][nj], al[mi], bh[nj]);
                    MMA16816(acc[mi][nj], ah[mi], bl[nj]);
                }
        }
    }

#pragma unroll
    for (int mi = 0; mi < 4; mi++) {
        const int r0 = bm0 + mi * 16 + (lane >> 2);
#pragma unroll
        for (int nj = 0; nj < 4; nj++) {
            const int col = bn0 + wid * 32 + nj * 8 + (lane & 3) * 2;
            const float b0 = bias[col], b1 = bias[col + 1];
            float o0x = acc[mi][nj][0] + b0, o0y = acc[mi][nj][1] + b1;
            float o1x = acc[mi][nj][2] + b0, o1y = acc[mi][nj][3] + b1;
            if (SPLIT) {
                uint32_t h0 = pack_hi(o0x, o0y);
                uint32_t h1 = pack_hi(o1x, o1y);
                *(uint32_t*)(Ch + (size_t)r0 * H_ + col)       = h0;
                *(uint32_t*)(Ch + (size_t)(r0 + 8) * H_ + col) = h1;
                *(uint32_t*)(Cl + (size_t)r0 * H_ + col)       = pack_lo(o0x, o0y, h0);
                *(uint32_t*)(Cl + (size_t)(r0 + 8) * H_ + col) = pack_lo(o1x, o1y, h1);
            } else {
                *(float2*)(C + (size_t)r0 * H_ + col)       = make_float2(o0x, o0y);
                *(float2*)(C + (size_t)(r0 + 8) * H_ + col) = make_float2(o1x, o1y);
            }
        }
    }
}

__global__ __launch_bounds__(128, 2)
void qkv_hl(const float* __restrict__ bq, const float* __restrict__ bk,
            const float* __restrict__ bv)
{
    extern __shared__ char gsm[];
    const __nv_bfloat16 *Ah, *Al, *Wh, *Wl;
    const float* bias;
    __nv_bfloat16 *Ch, *Cl;
    if (blockIdx.z == 0)      { Ah = g_xqh; Al = g_xql; Wh = g_wqh; Wl = g_wql; bias = bq; Ch = g_qh; Cl = g_ql; }
    else if (blockIdx.z == 1) { Ah = g_xkh; Al = g_xkl; Wh = g_wkh; Wl = g_wkl; bias = bk; Ch = g_kh; Cl = g_kl; }
    else                      { Ah = g_xvh; Al = g_xvl; Wh = g_wvh; Wl = g_wvl; bias = bv; Ch = g_vh; Cl = g_vl; }
    gemm_hl_body<1>(Ah, Al, Wh, Wl, bias, nullptr, Ch, Cl, gsm,
                    blockIdx.y * 64, blockIdx.x * 128);
}

__global__ __launch_bounds__(128, 2)
void gemm_o_hl(const float* __restrict__ bias, float* __restrict__ C)
{
    extern __shared__ char gsm[];
    gemm_hl_body<0>(g_ah, g_al, g_woh, g_wol, bias, C, nullptr, nullptr, gsm,
                    blockIdx.y * 64, blockIdx.x * 128);
}

// ===========================================================================
// Tensor-core flash attention: BQ=64, 128 threads (4 warps), 2-stage
// swizzled K/V staging (64 KB smem) -> 2 CTAs/SM. One barrier per tile.
// ===========================================================================
#define AT_TILE_B  (64 * 128)
#define AT_STAGE_B (4 * AT_TILE_B)      // 32768 B
#define ATTN_SMEM  (2 * AT_STAGE_B)     // 65536 B

__device__ __forceinline__ void attn_issue(
    uint32_t stage, const __nv_bfloat16* Kh, const __nv_bfloat16* Kl,
    const __nv_bfloat16* Vh, const __nv_bfloat16* Vl, int tid)
{
    const __nv_bfloat16* srcs[4] = { Kh, Kl, Vh, Vl };
#pragma unroll
    for (int t = 0; t < 4; t++) {
        const uint32_t db = stage + t * AT_TILE_B;
        const __nv_bfloat16* sb = srcs[t];
#pragma unroll
        for (int j = 0; j < 4; j++) {
            const int idx = tid + j * 128;
            const int row = idx >> 3;
            const int c   = idx & 7;
            const uint32_t dst = db + row * 128 + ((c * 16) ^ ((row & 7) << 4));
            CPA16(dst, sb + (size_t)row * H_ + c * 8);
        }
    }
}

__global__ __launch_bounds__(128, 2)
void attn_tc(const int* __restrict__ mask)
{
    extern __shared__ char asmem[];
    __shared__ uint32_t s_mb[32];

    const int tid  = threadIdx.x;
    const int wid  = tid >> 5;          // 0..3
    const int lane = tid & 31;
    const int qt = blockIdx.x;          // 16 tiles of 64 q-rows
    const int h  = blockIdx.y;
    const int b  = blockIdx.z;

    const uint32_t ubase = smem_u32(asmem);
    const uint32_t lswz  = (uint32_t)((lane & 7) << 4);
    const uint32_t kRow0 = (uint32_t)((((lane >> 4) & 1) * 8 + (lane & 7)) * 128);
    const uint32_t kCol  = ((uint32_t)(((lane >> 3) & 1) * 16)) ^ lswz;
    const uint32_t vRow0 = (uint32_t)((lane & 15) * 128);

    const int r0 = wid * 16 + (lane >> 2);
    const size_t qoff = ((size_t)(b * S_ + qt * 64)) * H_ + h * HD_;
    const __nv_bfloat16* Qhb = g_qh + qoff;
    const __nv_bfloat16* Qlb = g_ql + qoff;
    uint32_t qh[4][4], ql[4][4];
#pragma unroll
    for (int ks = 0; ks < 4; ks++) {
        const int kb = ks * 16 + (lane & 3) * 2;
        qh[ks][0] = *(const uint32_t*)(Qhb + (size_t)r0 * H_ + kb);
        qh[ks][1] = *(const uint32_t*)(Qhb + (size_t)(r0 + 8) * H_ + kb);
        qh[ks][2] = *(const uint32_t*)(Qhb + (size_t)r0 * H_ + kb + 8);
        qh[ks][3] = *(const uint32_t*)(Qhb + (size_t)(r0 + 8) * H_ + kb + 8);
        ql[ks][0] = *(const uint32_t*)(Qlb + (size_t)r0 * H_ + kb);
        ql[ks][1] = *(const uint32_t*)(Qlb + (size_t)(r0 + 8) * H_ + kb);
        ql[ks][2] = *(const uint32_t*)(Qlb + (size_t)r0 * H_ + kb + 8);
        ql[ks][3] = *(const uint32_t*)(Qlb + (size_t)(r0 + 8) * H_ + kb + 8);
    }

    // mask ballots: 4 warps x 8 words = 32 words
    {
        int mv[8];
#pragma unroll
        for (int j = 0; j < 8; j++)
            mv[j] = mask[(size_t)b * S_ + (wid * 8 + j) * 32 + lane];
#pragma unroll
        for (int j = 0; j < 8; j++) {
            unsigned bv = __ballot_sync(0xffffffffu, mv[j] != 0);
            if (lane == 0) s_mb[wid * 8 + j] = bv;
        }
    }

    float oacc[8][4];
#pragma unroll
    for (int nj = 0; nj < 8; nj++)
#pragma unroll
        for (int e = 0; e < 4; e++) oacc[nj][e] = 0.f;
    float m0 = -1e30f, m1 = -1e30f, l0 = 0.f, l1 = 0.f;

    const size_t koff = (size_t)b * S_ * H_ + h * HD_;
    const __nv_bfloat16* Khb = g_kh + koff;
    const __nv_bfloat16* Klb = g_kl + koff;
    const __nv_bfloat16* Vhb = g_vh + koff;
    const __nv_bfloat16* Vlb = g_vl + koff;

    // prologue: stage 0
    attn_issue(ubase, Khb, Klb, Vhb, Vlb, tid);
    CP_COMMIT();

    for (int kt = 0; kt < 16; kt++) {
        CP_WAIT(0);
        __syncthreads();
        if (kt < 15) {
            const size_t toff = (size_t)(kt + 1) * 64 * H_;
            attn_issue(ubase + (uint32_t)((kt + 1) & 1) * AT_STAGE_B,
                       Khb + toff, Klb + toff, Vhb + toff, Vlb + toff, tid);
            CP_COMMIT();
        }
        const uint32_t mw0 = s_mb[2 * kt];
        const uint32_t mw1 = s_mb[2 * kt + 1];
        const uint32_t ub  = ubase + (uint32_t)(kt & 1) * AT_STAGE_B;
        const uint32_t bKh = ub;
        const uint32_t bKl = ub + AT_TILE_B;
        const uint32_t bVh = ub + 2 * AT_TILE_B;
        const uint32_t bVl = ub + 3 * AT_TILE_B;

        // ---- S = Q K^T ----
        float sacc[8][4];
#pragma unroll
        for (int nj = 0; nj < 8; nj++)
#pragma unroll
            for (int e = 0; e < 4; e++) sacc[nj][e] = 0.f;

#pragma unroll
        for (int ks = 0; ks < 4; ks++) {
            const uint32_t kC = kCol ^ (uint32_t)(ks * 32);
            uint32_t bh[8][2], bl[8][2];
#pragma unroll
            for (int g = 0; g < 4; g++) {
                const uint32_t rowb = kRow0 + (uint32_t)(g * 16 * 128) + kC;
                LDMX4(bh[2 * g][0], bh[2 * g][1], bh[2 * g + 1][0], bh[2 * g + 1][1], bKh + rowb);
                LDMX4(bl[2 * g][0], bl[2 * g][1], bl[2 * g + 1][0], bl[2 * g + 1][1], bKl + rowb);
            }
#pragma unroll
            for (int nj = 0; nj < 8; nj++) {
                MMA16816(sacc[nj], qh[ks], bh[nj]);
                MMA16816(sacc[nj], ql[ks], bh[nj]);
                MMA16816(sacc[nj], qh[ks], bl[nj]);
            }
        }

        // ---- per-tile softmax ----
        const int shb = (lane & 3) * 2;
        float mx0 = -1e30f, mx1 = -1e30f;
#pragma unroll
        for (int nj = 0; nj < 8; nj++) {
            const uint32_t w = (nj < 4) ? mw0 : mw1;
            const int sh = (nj & 3) * 8 + shb;
            const bool k0 = (w >> sh) & 1;
            const bool k1 = (w >> (sh + 1)) & 1;
            float s0 = k0 ? -1e30f : sacc[nj][0] * 0.03125f;
            float s1 = k1 ? -1e30f : sacc[nj][1] * 0.03125f;
            float s2 = k0 ? -1e30f : sacc[nj][2] * 0.03125f;
            float s3 = k1 ? -1e30f : sacc[nj][3] * 0.03125f;
            sacc[nj][0] = s0; sacc[nj][1] = s1; sacc[nj][2] = s2; sacc[nj][3] = s3;
            mx0 = fmaxf(mx0, fmaxf(s0, s1));
            mx1 = fmaxf(mx1, fmaxf(s2, s3));
        }
        mx0 = fmaxf(mx0, __shfl_xor_sync(0xffffffffu, mx0, 1));
        mx0 = fmaxf(mx0, __shfl_xor_sync(0xffffffffu, mx0, 2));
        mx1 = fmaxf(mx1, __shfl_xor_sync(0xffffffffu, mx1, 1));
        mx1 = fmaxf(mx1, __shfl_xor_sync(0xffffffffu, mx1, 2));

        const float nm0 = fmaxf(m0, mx0);
        const float nm1 = fmaxf(m1, mx1);
        const float f0 = __expf(m0 - nm0);
        const float f1 = __expf(m1 - nm1);
        m0 = nm0; m1 = nm1;
        l0 *= f0;  l1 *= f1;
#pragma unroll
        for (int nj = 0; nj < 8; nj++) {
            oacc[nj][0] *= f0; oacc[nj][1] *= f0;
            oacc[nj][2] *= f1; oacc[nj][3] *= f1;
        }

        uint32_t pHa[8], pHb[8], pLa[8], pLb[8];
        float ps0 = 0.f, ps1 = 0.f;
#pragma unroll
        for (int nj = 0; nj < 8; nj++) {
            float p0 = __expf(sacc[nj][0] - nm0);
            float p1 = __expf(sacc[nj][1] - nm0);
            float p2 = __expf(sacc[nj][2] - nm1);
            float p3 = __expf(sacc[nj][3] - nm1);
            ps0 += p0 + p1;
            ps1 += p2 + p3;
            pHa[nj] = pack_hi(p0, p1);  pLa[nj] = pack_lo(p0, p1, pHa[nj]);
            pHb[nj] = pack_hi(p2, p3);  pLb[nj] = pack_lo(p2, p3, pHb[nj]);
        }
        l0 += ps0;
        l1 += ps1;

        // ---- O += P V ----
#pragma unroll
        for (int kk = 0; kk < 4; kk++) {
            uint32_t aH[4] = { pHa[2 * kk], pHb[2 * kk], pHa[2 * kk + 1], pHb[2 * kk + 1] };
            uint32_t aL[4] = { pLa[2 * kk], pLb[2 * kk], pLa[2 * kk + 1], pLb[2 * kk + 1] };
#pragma unroll
            for (int njp = 0; njp < 8; njp += 2) {
                const uint32_t colb =
                    ((uint32_t)((njp + ((lane >> 4) & 1)) * 16)) ^ lswz;
                const uint32_t rowb = vRow0 + (uint32_t)(kk * 16 * 128) + colb;
                uint32_t vh[2][2], vl[2][2];
                LDMX4T(vh[0][0], vh[0][1], vh[1][0], vh[1][1], bVh + rowb);
                LDMX4T(vl[0][0], vl[0][1], vl[1][0], vl[1][1], bVl + rowb);
                MMA16816(oacc[njp],     aH, vh[0]);
                MMA16816(oacc[njp],     aL, vh[0]);
                MMA16816(oacc[njp],     aH, vl[0]);
                MMA16816(oacc[njp + 1], aH, vh[1]);
                MMA16816(oacc[njp + 1], aL, vh[1]);
                MMA16816(oacc[njp + 1], aH, vl[1]);
            }
        }
    }

    l0 += __shfl_xor_sync(0xffffffffu, l0, 1);
    l0 += __shfl_xor_sync(0xffffffffu, l0, 2);
    l1 += __shfl_xor_sync(0xffffffffu, l1, 1);
    l1 += __shfl_xor_sync(0xffffffffu, l1, 2);
    const float rl0 = 1.f / l0;
    const float rl1 = 1.f / l1;

    __nv_bfloat16* Ahb = g_ah + qoff;
    __nv_bfloat16* Alb = g_al + qoff;
#pragma unroll
    for (int nj = 0; nj < 8; nj++) {
        const int colb = nj * 8 + (lane & 3) * 2;
        float x0 = oacc[nj][0] * rl0, y0 = oacc[nj][1] * rl0;
        float x1 = oacc[nj][2] * rl1, y1 = oacc[nj][3] * rl1;
        uint32_t h0 = pack_hi(x0, y0);
        uint32_t h1 = pack_hi(x1, y1);
        *(uint32_t*)(Ahb + (size_t)r0 * H_ + colb)       = h0;
        *(uint32_t*)(Ahb + (size_t)(r0 + 8) * H_ + colb) = h1;
        *(uint32_t*)(Alb + (size_t)r0 * H_ + colb)       = pack_lo(x0, y0, h0);
        *(uint32_t*)(Alb + (size_t)(r0 + 8) * H_ + colb) = pack_lo(x1, y1, h1);
    }
}

// ---------------------------------------------------------------------------
extern "C" void kernel_launch(void* const* d_in, const int* in_sizes, int n_in,
                              void* d_out, int out_size)
{
    const float* query = (const float*)d_in[0];
    const float* key   = (const float*)d_in[1];
    const float* value = (const float*)d_in[2];
    const int*   mask  = (const int*)d_in[3];

    const int wb = (n_in >= 13) ? 5 : 4;
    const float* Wq = (const float*)d_in[wb + 0];
    const float* bq = (const float*)d_in[wb + 1];
    const float* Wk = (const float*)d_in[wb + 2];
    const float* bk = (const float*)d_in[wb + 3];
    const float* Wv = (const float*)d_in[wb + 4];
    const float* bv = (const float*)d_in[wb + 5];
    const float* Wo = (const float*)d_in[wb + 6];
    const float* bo = (const float*)d_in[wb + 7];
    float* out = (float*)d_out;

    __nv_bfloat16 *xqh, *xql, *xkh, *xkl, *xvh, *xvl;
    cudaGetSymbolAddress((void**)&xqh, g_xqh); cudaGetSymbolAddress((void**)&xql, g_xql);
    cudaGetSymbolAddress((void**)&xkh, g_xkh); cudaGetSymbolAddress((void**)&xkl, g_xkl);
    cudaGetSymbolAddress((void**)&xvh, g_xvh); cudaGetSymbolAddress((void**)&xvl, g_xvl);

    cudaFuncSetAttribute(qkv_hl,    cudaFuncAttributeMaxDynamicSharedMemorySize, GEMM_SMEM);
    cudaFuncSetAttribute(gemm_o_hl, cudaFuncAttributeMaxDynamicSharedMemorySize, GEMM_SMEM);
    cudaFuncSetAttribute(attn_tc,   cudaFuncAttributeMaxDynamicSharedMemorySize, ATTN_SMEM);

    const int nBig16 = NBIG / 16;
    const int nWt16  = H_ * H_ / 16;
    conv_hl<<<2048, 256>>>(query, xqh, xql, nBig16);            // 0
    conv_hl<<<2048, 256>>>(key,   xkh, xkl, nBig16);            // 1
    conv_hl<<<2048, 256>>>(value, xvh, xvl, nBig16);            // 2
    conv_w4<<<dim3(128, 4), 256>>>(Wq, Wk, Wv, Wo, nWt16);      // 3

    dim3 qkvgrid(H_ / 128, MROWS / 64, 3);   // (8, 128, 3)
    qkv_hl<<<qkvgrid, 128, GEMM_SMEM>>>(bq, bk, bv);            // 4

    dim3 agrid(S_ / 64, NH_, B_);            // (16, 16, 8)
    attn_tc<<<agrid, 128, ATTN_SMEM>>>(mask);                   // 5

    dim3 ggrid(H_ / 128, MROWS / 64);        // (8, 128)
    gemm_o_hl<<<ggrid, 128, GEMM_SMEM>>>(bo, out);              // 6
}